// round 14
// baseline (speedup 1.0000x reference)
#include <cuda_runtime.h>
#include <cuda_fp16.h>
#include <cstdint>

#define T_LEN 2048
#define BSZ   2
#define DM    1024
#define NH    16
#define HD    64
#define EMB   1024
#define MROWS 4096
#define NELEM ((size_t)MROWS * DM)          // 4M elements per input tensor
#define LOG2E 1.4426950408889634f

// ---------------- scratch (allocation-free: device globals) ----------------
__device__ __half g_in[3 * NELEM];          // inputs fp16 (q,k,v)
__device__ __half g_wih[(size_t)3 * EMB * DM];  // in_proj_weight fp16
__device__ __half g_woh[(size_t)DM * EMB];      // out_proj_weight fp16
__device__ __half g_qh[(size_t)BSZ * NH * T_LEN * HD];  // q fp16 (scaled 1/8*log2e)
__device__ __half g_kh[(size_t)BSZ * NH * T_LEN * HD];  // k fp16
__device__ __half g_vh[(size_t)BSZ * NH * T_LEN * HD];  // v fp16
__device__ __half g_ah[NELEM];              // attn out fp16  [t*B+b][e]
__device__ int g_mask_nz;                   // 1 if mask has any nonzero

// ============================ PTX helpers ===================================
__device__ __forceinline__ uint32_t su32(const void* p) {
    uint32_t a;
    asm("{ .reg .u64 t; cvta.to.shared.u64 t, %1; cvt.u32.u64 %0, t; }"
        : "=r"(a) : "l"(p));
    return a;
}
__device__ __forceinline__ void cpa(uint32_t s, const void* g) {
    asm volatile("cp.async.cg.shared.global [%0], [%1], 16;" :: "r"(s), "l"(g));
}
__device__ __forceinline__ void cp_commit() {
    asm volatile("cp.async.commit_group;" ::: "memory");
}
__device__ __forceinline__ void cp_wait0() {
    asm volatile("cp.async.wait_group 0;" ::: "memory");
}
__device__ __forceinline__ void cp_wait1() {
    asm volatile("cp.async.wait_group 1;" ::: "memory");
}
__device__ __forceinline__ void cp_wait2() {
    asm volatile("cp.async.wait_group 2;" ::: "memory");
}
__device__ __forceinline__ void ldsm4(uint32_t r[4], uint32_t a) {
    asm volatile("ldmatrix.sync.aligned.m8n8.x4.shared.b16 {%0,%1,%2,%3}, [%4];"
                 : "=r"(r[0]), "=r"(r[1]), "=r"(r[2]), "=r"(r[3]) : "r"(a));
}
__device__ __forceinline__ void ldsm4t(uint32_t r[4], uint32_t a) {
    asm volatile("ldmatrix.sync.aligned.m8n8.x4.trans.shared.b16 {%0,%1,%2,%3}, [%4];"
                 : "=r"(r[0]), "=r"(r[1]), "=r"(r[2]), "=r"(r[3]) : "r"(a));
}
__device__ __forceinline__ void mma_f16(float c[4], const uint32_t a[4],
                                        const uint32_t b[2]) {
    asm volatile(
        "mma.sync.aligned.m16n8k16.row.col.f32.f16.f16.f32 "
        "{%0,%1,%2,%3}, {%4,%5,%6,%7}, {%8,%9}, {%0,%1,%2,%3};"
        : "+f"(c[0]), "+f"(c[1]), "+f"(c[2]), "+f"(c[3])
        : "r"(a[0]), "r"(a[1]), "r"(a[2]), "r"(a[3]), "r"(b[0]), "r"(b[1]));
}
__device__ __forceinline__ float ex2(float x) {
    float y;
    asm("ex2.approx.f32 %0, %1;" : "=f"(y) : "f"(x));
    return y;
}
__device__ __forceinline__ uint32_t h2ex2(uint32_t x) {
    uint32_t y;
    asm("ex2.approx.f16x2 %0, %1;" : "=r"(y) : "r"(x));
    return y;
}
__device__ __forceinline__ uint32_t hadd2(uint32_t a, uint32_t b) {
    uint32_t d;
    asm("add.f16x2 %0, %1, %2;" : "=r"(d) : "r"(a), "r"(b));
    return d;
}
__device__ __forceinline__ uint32_t hmul2(uint32_t a, uint32_t b) {
    uint32_t d;
    asm("mul.f16x2 %0, %1, %2;" : "=r"(d) : "r"(a), "r"(b));
    return d;
}
__device__ __forceinline__ float2 h2f2(uint32_t h) {
    __half2 v = *reinterpret_cast<__half2*>(&h);
    return __half22float2(v);
}
__device__ __forceinline__ uint32_t fpk(float a, float b) {
    __half2 t = __floats2half2_rn(a, b);
    return *reinterpret_cast<uint32_t*>(&t);
}

// ============================================================================
// Prep: one kernel converts inputs + weights AND scans the mask.
// ============================================================================
__global__ __launch_bounds__(256) void prep_all(
    const float* __restrict__ q, const float* __restrict__ k,
    const float* __restrict__ v, const float* __restrict__ in_w,
    const float* __restrict__ out_w, const float* __restrict__ mask)
{
    const int b = blockIdx.x;
    if (b < 12288) {
        const int z = b >> 12;                 // /4096
        const float* s = (z == 0) ? q : (z == 1) ? k : v;
        const size_t i = ((size_t)(b & 4095) * 256 + threadIdx.x) * 4;
        float4 x = *(const float4*)(s + i);
        uint2 H;
        H.x = fpk(x.x, x.y);
        H.y = fpk(x.z, x.w);
        *(uint2*)(g_in + (size_t)z * NELEM + i) = H;
    } else if (b < 16384) {
        const size_t i = ((size_t)(b - 12288) * 256 + threadIdx.x) * 4;
        const size_t NW = (size_t)3 * EMB * DM;
        const float* s = (i < NW) ? (in_w + i) : (out_w + (i - NW));
        __half* d = (i < NW) ? (g_wih + i) : (g_woh + (i - NW));
        float4 x = *(const float4*)s;
        uint2 H;
        H.x = fpk(x.x, x.y);
        H.y = fpk(x.z, x.w);
        *(uint2*)d = H;
    } else {
        const size_t i = ((size_t)(b - 16384) * 256 + threadIdx.x) * 4;
        float4 x = *(const float4*)(mask + i);
        if (x.x != 0.f || x.y != 0.f || x.z != 0.f || x.w != 0.f) g_mask_nz = 1;
    }
}

__global__ void mask_flag_reset() { g_mask_nz = 0; }

// ============================================================================
// GEMM core (TN, single fp16): CTA 128x128, chunk K=32, 3-stage cp.async,
// staging issued at TOP of iteration -> single __syncthreads per chunk.
// smem/stage: A[128x32] W[128x32] fp16, row stride 80B. 8 warps = 2m x 4n.
// ============================================================================
#define GRS 80
#define S_A 0
#define S_W 10240
#define G_STAGE 20480
#define G_SMEM (3 * G_STAGE)

__device__ __forceinline__ void g_load(uint32_t sb, const __half* A,
                                       const __half* Wg,
                                       int m0, int n0, int c, int buf, int tid)
{
    const uint32_t st = sb + buf * G_STAGE;
    const int k0 = c * 32;
    #pragma unroll
    for (int i = 0; i < 2; i++) {
        const int idx = tid + i * 256;          // 0..511
        const int row = idx >> 2, cc = idx & 3;
        const uint32_t o = row * GRS + cc * 16;
        cpa(st + S_A + o, A  + (size_t)(m0 + row) * DM + k0 + cc * 8);
        cpa(st + S_W + o, Wg + (size_t)(n0 + row) * DM + k0 + cc * 8);
    }
    cp_commit();
}

__device__ __forceinline__ void gemm_core(
    const __half* __restrict__ A, const __half* __restrict__ Wg,
    int m0, int n0, uint32_t sb, float (&acc)[4][4][4])
{
    const int tid = threadIdx.x, lane = tid & 31, wid = tid >> 5;
    const int mh = wid & 1;          // 0..1 : 64-row half
    const int nq = wid >> 1;         // 0..3 : 32-col quad

    #pragma unroll
    for (int i = 0; i < 4; i++)
        #pragma unroll
        for (int j = 0; j < 4; j++)
            #pragma unroll
            for (int v = 0; v < 4; v++) acc[i][j][v] = 0.f;

    g_load(sb, A, Wg, m0, n0, 0, 0, tid);
    g_load(sb, A, Wg, m0, n0, 1, 1, tid);

    const int a_l = (mh * 64 + (lane & 15)) * GRS + ((lane >> 4) << 3) * 2;
    const int b_l = (nq * 32 + ((lane >> 4) << 3) + (lane & 7)) * GRS + (lane & 8) * 2;

    int b_rd = 0, b_wr = 2;
    #pragma unroll 1
    for (int c = 0; c < 32; c++) {
        if (c == 31) cp_wait0(); else cp_wait1();
        __syncthreads();
        if (c + 2 < 32) g_load(sb, A, Wg, m0, n0, c + 2, b_wr, tid);

        const uint32_t st = sb + b_rd * G_STAGE;
        #pragma unroll
        for (int kk = 0; kk < 2; kk++) {
            uint32_t af[4][4], bf[4][2];
            #pragma unroll
            for (int mi = 0; mi < 4; mi++)
                ldsm4(af[mi], st + S_A + a_l + mi * 16 * GRS + kk * 32);
            #pragma unroll
            for (int np = 0; np < 2; np++) {
                uint32_t t[4];
                ldsm4(t, st + S_W + b_l + np * 16 * GRS + kk * 32);
                bf[np * 2][0] = t[0]; bf[np * 2][1] = t[1];
                bf[np * 2 + 1][0] = t[2]; bf[np * 2 + 1][1] = t[3];
            }
            #pragma unroll
            for (int mi = 0; mi < 4; mi++)
                #pragma unroll
                for (int ni = 0; ni < 4; ni++)
                    mma_f16(acc[mi][ni], af[mi], bf[ni]);
        }
        b_rd = (b_rd == 2) ? 0 : b_rd + 1;
        b_wr = (b_wr == 2) ? 0 : b_wr + 1;
    }
}

// -------- QKV projection: z selects q/k/v; writes fp16 per-head -------------
__global__ __launch_bounds__(256, 2) void qkv_gemm(const float* __restrict__ bias)
{
    extern __shared__ char sm[];
    const int z = blockIdx.z;
    const __half* A  = g_in + (size_t)z * NELEM;
    const __half* Wg = g_wih + (size_t)z * EMB * DM;
    const float* bz = bias + z * EMB;

    const int m0 = blockIdx.y * 128;
    const int n0 = blockIdx.x * 128;

    float acc[4][4][4];
    gemm_core(A, Wg, m0, n0, su32(sm), acc);

    const int lane = threadIdx.x & 31, wid = threadIdx.x >> 5;
    const int mh = wid & 1, nq = wid >> 1;
    const int g = lane >> 2, t4 = lane & 3;

    __half* dst = (z == 0) ? g_qh : (z == 1) ? g_kh : g_vh;
    const float sc = (z == 0) ? (0.125f * LOG2E) : 1.0f;   // exp2-domain scores

    #pragma unroll
    for (int mi = 0; mi < 4; mi++) {
        #pragma unroll
        for (int ni = 0; ni < 4; ni++) {
            const int mrow = m0 + mh * 64 + mi * 16 + g;
            const int ncol = n0 + nq * 32 + ni * 8 + t4 * 2;
            const float b0 = __ldg(&bz[ncol]), b1 = __ldg(&bz[ncol + 1]);
            const int h = ncol >> 6, d = ncol & 63;
            #pragma unroll
            for (int rr = 0; rr < 2; rr++) {
                const int m = mrow + rr * 8;
                const int t = m >> 1, b = m & 1;
                const float v0 = (acc[mi][ni][rr * 2 + 0] + b0) * sc;
                const float v1 = (acc[mi][ni][rr * 2 + 1] + b1) * sc;
                const size_t idx = ((size_t)(b * NH + h) * T_LEN + t) * HD + d;
                *(uint32_t*)(dst + idx) = fpk(v0, v1);
            }
        }
    }
}

// -------- Output projection: C = attn(fp16) @ Wo^T + bo ---------------------
__global__ __launch_bounds__(256, 2) void out_gemm(const float* __restrict__ bias,
                                                   float* __restrict__ C)
{
    extern __shared__ char sm[];
    const int m0 = blockIdx.y * 128;
    const int n0 = blockIdx.x * 128;

    float acc[4][4][4];
    gemm_core(g_ah, g_woh, m0, n0, su32(sm), acc);

    const int lane = threadIdx.x & 31, wid = threadIdx.x >> 5;
    const int mh = wid & 1, nq = wid >> 1;
    const int g = lane >> 2, t4 = lane & 3;

    #pragma unroll
    for (int mi = 0; mi < 4; mi++) {
        #pragma unroll
        for (int ni = 0; ni < 4; ni++) {
            const int mrow = m0 + mh * 64 + mi * 16 + g;
            const int ncol = n0 + nq * 32 + ni * 8 + t4 * 2;
            const float b0 = __ldg(&bias[ncol]), b1 = __ldg(&bias[ncol + 1]);
            #pragma unroll
            for (int rr = 0; rr < 2; rr++) {
                const int m = mrow + rr * 8;
                float2 v;
                v.x = acc[mi][ni][rr * 2 + 0] + b0;
                v.y = acc[mi][ni][rr * 2 + 1] + b1;
                *(float2*)(C + (size_t)m * DM + ncol) = v;
            }
        }
    }
}

// ============================================================================
// Flash attention, fp16 mma, 4 warps x 32 q-rows, 2-stage KV (round-12 cfg).
// NEW: speculative softmax — p = exp2(s - mr_old) issued in parallel with the
// shuffle max reduction; rare rescale of p by c when the max advances.
// ============================================================================
#define ARS 144
#define F_Q  0
#define F_KV 18432
#define F_KVS 18432          // per stage: K 9216 + V 9216
#define F_SMEM (F_KV + 2 * F_KVS)   // 55296

__device__ __forceinline__ void f_stage_kv(uint32_t sb, size_t hbase, int it, int tid)
{
    const uint32_t st = sb + F_KV + (it & 1) * F_KVS;
    const int s0 = it * 64;
    #pragma unroll
    for (int i = 0; i < 4; i++) {
        const int idx = tid + i * 128;          // 0..511
        const int row = idx >> 3, cc = idx & 7;
        const size_t src = (hbase + s0 + row) * HD + cc * 8;
        cpa(st + row * ARS + cc * 16, g_kh + src);
        cpa(st + 9216 + row * ARS + cc * 16, g_vh + src);
    }
    cp_commit();
}

__global__ __launch_bounds__(128, 2) void flash_mma(const float* __restrict__ mask)
{
    extern __shared__ char sm[];
    const uint32_t sb = su32(sm);
    const int tid = threadIdx.x, lane = tid & 31, w = tid >> 5;   // 4 warps
    const int bh = blockIdx.y, qt = blockIdx.x;
    const int g = lane >> 2, t4 = lane & 3;
    const size_t hbase = (size_t)bh * T_LEN;
    const int mnz = g_mask_nz;

    {   // stage Q (128 rows)
        const size_t qb = (hbase + qt * 128) * HD;
        #pragma unroll
        for (int i = 0; i < 8; i++) {
            const int idx = tid + i * 128;      // 0..1023
            const int row = idx >> 3, cc = idx & 7;
            cpa(sb + F_Q + row * ARS + cc * 16, g_qh + qb + (size_t)row * HD + cc * 8);
        }
        cp_commit();
    }
    f_stage_kv(sb, hbase, 0, tid);
    f_stage_kv(sb, hbase, 1, tid);
    cp_wait2();
    __syncthreads();

    // q fragments: two m16 groups per warp (rows w*32+mi*16 .. +15)
    uint32_t qf[2][4][4];
    #pragma unroll
    for (int mi = 0; mi < 2; mi++)
        #pragma unroll
        for (int j = 0; j < 4; j++)
            ldsm4(qf[mi][j], sb + F_Q + (w * 32 + mi * 16 + (lane & 15)) * ARS +
                             (j * 16 + ((lane >> 4) << 3)) * 2);

    float oacc[2][8][4];
    #pragma unroll
    for (int mi = 0; mi < 2; mi++)
        #pragma unroll
        for (int i = 0; i < 8; i++)
            #pragma unroll
            for (int v = 0; v < 4; v++) oacc[mi][i][v] = 0.f;
    float mr[2][2] = {{-1e30f, -1e30f}, {-1e30f, -1e30f}};
    float lr[2][2] = {{0.f, 0.f}, {0.f, 0.f}};

    const int tq = qt * 128 + w * 32 + g;
    const float* mrow[2][2];
    mrow[0][0] = mask + (size_t)tq * T_LEN;
    mrow[0][1] = mrow[0][0] + (size_t)8 * T_LEN;
    mrow[1][0] = mrow[0][0] + (size_t)16 * T_LEN;
    mrow[1][1] = mrow[0][0] + (size_t)24 * T_LEN;

    #pragma unroll 1
    for (int it = 0; it < 32; it++) {
        if (it == 31) cp_wait0(); else cp_wait1();
        __syncthreads();
        const uint32_t kst = sb + F_KV + (it & 1) * F_KVS;
        const uint32_t vst = kst + 9216;

        // ---- S' = (Q*log2e/8) K^T : K fragments shared by both m-groups ----
        float sacc[2][8][4];
        #pragma unroll
        for (int mi = 0; mi < 2; mi++)
            #pragma unroll
            for (int i = 0; i < 8; i++)
                #pragma unroll
                for (int v = 0; v < 4; v++) sacc[mi][i][v] = 0.f;

        #pragma unroll
        for (int j = 0; j < 4; j++) {
            uint32_t kb[8][2];
            #pragma unroll
            for (int np = 0; np < 4; np++) {
                uint32_t t[4];
                ldsm4(t, kst + (np * 16 + ((lane >> 4) << 3) + (lane & 7)) * ARS +
                         (j * 16 + (lane & 8)) * 2);
                kb[np * 2][0] = t[0]; kb[np * 2][1] = t[1];
                kb[np * 2 + 1][0] = t[2]; kb[np * 2 + 1][1] = t[3];
            }
            #pragma unroll
            for (int mi = 0; mi < 2; mi++)
                #pragma unroll
                for (int jn = 0; jn < 8; jn++)
                    mma_f16(sacc[mi][jn], qf[mi][j], kb[jn]);
        }

        // ---- mask + online softmax (speculative exp2, lazy rescale) ----
        const int s0 = it * 64;
        uint32_t p01[2][8], p23[2][8];
        #pragma unroll
        for (int mi = 0; mi < 2; mi++) {
            if (mnz) {
                #pragma unroll
                for (int jn = 0; jn < 8; jn++) {
                    const int sc = s0 + jn * 8 + t4 * 2;
                    float2 ma = *(const float2*)(mrow[mi][0] + sc);
                    float2 mb = *(const float2*)(mrow[mi][1] + sc);
                    sacc[mi][jn][0] = fmaf(ma.x, LOG2E, sacc[mi][jn][0]);
                    sacc[mi][jn][1] = fmaf(ma.y, LOG2E, sacc[mi][jn][1]);
                    sacc[mi][jn][2] = fmaf(mb.x, LOG2E, sacc[mi][jn][2]);
                    sacc[mi][jn][3] = fmaf(mb.y, LOG2E, sacc[mi][jn][3]);
                }
            }
            float mx0 = -1e30f, mx1 = -1e30f;
            #pragma unroll
            for (int jn = 0; jn < 8; jn++) {
                mx0 = fmaxf(mx0, fmaxf(sacc[mi][jn][0], sacc[mi][jn][1]));
                mx1 = fmaxf(mx1, fmaxf(sacc[mi][jn][2], sacc[mi][jn][3]));
            }

            if (it == 0) {
                // non-speculative first tile (mr uninitialized)
                mx0 = fmaxf(mx0, __shfl_xor_sync(0xffffffffu, mx0, 1));
                mx0 = fmaxf(mx0, __shfl_xor_sync(0xffffffffu, mx0, 2));
                mx1 = fmaxf(mx1, __shfl_xor_sync(0xffffffffu, mx1, 1));
                mx1 = fmaxf(mx1, __shfl_xor_sync(0xffffffffu, mx1, 2));
                mr[mi][0] = mx0;
                mr[mi][1] = mx1;
                #pragma unroll
                for (int jn = 0; jn < 8; jn++) {
                    p01[mi][jn] = h2ex2(fpk(sacc[mi][jn][0] - mx0,
                                            sacc[mi][jn][1] - mx0));
                    p23[mi][jn] = h2ex2(fpk(sacc[mi][jn][2] - mx1,
                                            sacc[mi][jn][3] - mx1));
                }
            } else {
                // speculative: exps with OLD mr, overlapped with shuffle max
                const float om0 = mr[mi][0], om1 = mr[mi][1];
                #pragma unroll
                for (int jn = 0; jn < 8; jn++) {
                    p01[mi][jn] = h2ex2(fpk(sacc[mi][jn][0] - om0,
                                            sacc[mi][jn][1] - om0));
                    p23[mi][jn] = h2ex2(fpk(sacc[mi][jn][2] - om1,
                                            sacc[mi][jn][3] - om1));
                }
                mx0 = fmaxf(mx0, __shfl_xor_sync(0xffffffffu, mx0, 1));
                mx0 = fmaxf(mx0, __shfl_xor_sync(0xffffffffu, mx0, 2));
                mx1 = fmaxf(mx1, __shfl_xor_sync(0xffffffffu, mx1, 1));
                mx1 = fmaxf(mx1, __shfl_xor_sync(0xffffffffu, mx1, 2));

                if (mx0 > om0) {                 // rare: max advanced
                    const float c0 = ex2(om0 - mx0);
                    mr[mi][0] = mx0;
                    lr[mi][0] *= c0;
                    const uint32_t ch = fpk(c0, c0);
                    #pragma unroll
                    for (int jd = 0; jd < 8; jd++) {
                        oacc[mi][jd][0] *= c0; oacc[mi][jd][1] *= c0;
                        p01[mi][jd] = hmul2(p01[mi][jd], ch);
                    }
                }
                if (mx1 > om1) {
                    const float c1 = ex2(om1 - mx1);
                    mr[mi][1] = mx1;
                    lr[mi][1] *= c1;
                    const uint32_t ch = fpk(c1, c1);
                    #pragma unroll
                    for (int jd = 0; jd < 8; jd++) {
                        oacc[mi][jd][2] *= c1; oacc[mi][jd][3] *= c1;
                        p23[mi][jd] = hmul2(p23[mi][jd], ch);
                    }
                }
            }
            #pragma unroll
            for (int jn = 0; jn < 8; jn += 2) {
                float2 f0 = h2f2(hadd2(p01[mi][jn], p01[mi][jn + 1]));
                float2 f1 = h2f2(hadd2(p23[mi][jn], p23[mi][jn + 1]));
                lr[mi][0] += f0.x + f0.y;
                lr[mi][1] += f1.x + f1.y;
            }
        }

        // ---- O += P V : V fragments shared by both m-groups ----
        #pragma unroll
        for (int js = 0; js < 4; js++) {
            uint32_t vb[8][2];
            #pragma unroll
            for (int dp = 0; dp < 4; dp++) {
                uint32_t t[4];
                ldsm4t(t, vst + (js * 16 + (lane & 15)) * ARS +
                          (dp * 16 + ((lane >> 4) << 3)) * 2);
                vb[dp * 2][0] = t[0]; vb[dp * 2][1] = t[1];
                vb[dp * 2 + 1][0] = t[2]; vb[dp * 2 + 1][1] = t[3];
            }
            #pragma unroll
            for (int mi = 0; mi < 2; mi++) {
                uint32_t pf[4];
                pf[0] = p01[mi][2 * js];
                pf[1] = p23[mi][2 * js];
                pf[2] = p01[mi][2 * js + 1];
                pf[3] = p23[mi][2 * js + 1];
                #pragma unroll
                for (int jd = 0; jd < 8; jd++)
                    mma_f16(oacc[mi][jd], pf, vb[jd]);
            }
        }
        __syncthreads();
        if (it + 2 < 32) f_stage_kv(sb, hbase, it + 2, tid);
    }

    const int b = bh >> 4, h = bh & 15;
    #pragma unroll
    for (int mi = 0; mi < 2; mi++) {
        float l0 = lr[mi][0], l1 = lr[mi][1];
        l0 += __shfl_xor_sync(0xffffffffu, l0, 1);
        l0 += __shfl_xor_sync(0xffffffffu, l0, 2);
        l1 += __shfl_xor_sync(0xffffffffu, l1, 1);
        l1 += __shfl_xor_sync(0xffffffffu, l1, 2);
        const float i0 = 1.0f / l0, i1 = 1.0f / l1;

        const int trow = tq + mi * 16;
        const size_t r0 = ((size_t)trow * BSZ + b) * EMB + h * HD;
        const size_t r1 = ((size_t)(trow + 8) * BSZ + b) * EMB + h * HD;
        #pragma unroll
        for (int jd = 0; jd < 8; jd++) {
            const int d = jd * 8 + t4 * 2;
            *(uint32_t*)(g_ah + r0 + d) = fpk(oacc[mi][jd][0] * i0,
                                              oacc[mi][jd][1] * i0);
            *(uint32_t*)(g_ah + r1 + d) = fpk(oacc[mi][jd][2] * i1,
                                              oacc[mi][jd][3] * i1);
        }
    }
}

// ============================================================================
// Launch
// ============================================================================
extern "C" void kernel_launch(void* const* d_in, const int* in_sizes, int n_in,
                              void* d_out, int out_size)
{
    const float* query  = (const float*)d_in[0];
    const float* key    = (const float*)d_in[1];
    const float* value  = (const float*)d_in[2];
    const float* mask   = (const float*)d_in[3];
    const float* in_w   = (const float*)d_in[4];
    const float* in_b   = (const float*)d_in[5];
    const float* out_w  = (const float*)d_in[6];
    const float* out_b  = (const float*)d_in[7];
    float* out = (float*)d_out;

    cudaFuncSetAttribute(qkv_gemm, cudaFuncAttributeMaxDynamicSharedMemorySize, G_SMEM);
    cudaFuncSetAttribute(out_gemm, cudaFuncAttributeMaxDynamicSharedMemorySize, G_SMEM);
    cudaFuncSetAttribute(flash_mma, cudaFuncAttributeMaxDynamicSharedMemorySize, F_SMEM);

    // 0) prep: reset flag, then convert inputs + weights + scan mask (1 kernel)
    mask_flag_reset<<<1, 1>>>();
    prep_all<<<20480, 256>>>(query, key, value, in_w, out_w, mask);

    // 1) QKV projection (fp16 mma, 128x128 tiles, 3-stage top-staged)
    qkv_gemm<<<dim3(EMB / 128, MROWS / 128, 3), 256, G_SMEM>>>(in_b);

    // 2) Attention (fp16 mma flash, 2-stage KV, speculative softmax)
    flash_mma<<<dim3(T_LEN / 128, BSZ * NH), 128, F_SMEM>>>(mask);

    // 3) Output projection (fp16 mma, 3-stage top-staged) -> d_out
    out_gemm<<<dim3(DM / 128, MROWS / 128), 256, G_SMEM>>>(out_b, out);
}

// round 15
// speedup vs baseline: 1.0163x; 1.0163x over previous
#include <cuda_runtime.h>
#include <cuda_fp16.h>
#include <cstdint>

#define T_LEN 2048
#define BSZ   2
#define DM    1024
#define NH    16
#define HD    64
#define EMB   1024
#define MROWS 4096
#define NELEM ((size_t)MROWS * DM)          // 4M elements per input tensor
#define LOG2E 1.4426950408889634f

// ---------------- scratch (allocation-free: device globals) ----------------
__device__ __half g_in[3 * NELEM];          // inputs fp16 (q,k,v)
__device__ __half g_wih[(size_t)3 * EMB * DM];  // in_proj_weight fp16
__device__ __half g_woh[(size_t)DM * EMB];      // out_proj_weight fp16
__device__ __half g_qh[(size_t)BSZ * NH * T_LEN * HD];  // q fp16 (scaled 1/8*log2e)
__device__ __half g_kh[(size_t)BSZ * NH * T_LEN * HD];  // k fp16
__device__ __half g_vh[(size_t)BSZ * NH * T_LEN * HD];  // v fp16
__device__ __half g_ah[NELEM];              // attn out fp16  [t*B+b][e]
__device__ int g_mask_nz;                   // 1 if mask has any nonzero

// ============================ PTX helpers ===================================
__device__ __forceinline__ uint32_t su32(const void* p) {
    uint32_t a;
    asm("{ .reg .u64 t; cvta.to.shared.u64 t, %1; cvt.u32.u64 %0, t; }"
        : "=r"(a) : "l"(p));
    return a;
}
__device__ __forceinline__ void cpa(uint32_t s, const void* g) {
    asm volatile("cp.async.cg.shared.global [%0], [%1], 16;" :: "r"(s), "l"(g));
}
__device__ __forceinline__ void cp_commit() {
    asm volatile("cp.async.commit_group;" ::: "memory");
}
__device__ __forceinline__ void cp_wait0() {
    asm volatile("cp.async.wait_group 0;" ::: "memory");
}
__device__ __forceinline__ void cp_wait1() {
    asm volatile("cp.async.wait_group 1;" ::: "memory");
}
__device__ __forceinline__ void cp_wait2() {
    asm volatile("cp.async.wait_group 2;" ::: "memory");
}
__device__ __forceinline__ void ldsm4(uint32_t r[4], uint32_t a) {
    asm volatile("ldmatrix.sync.aligned.m8n8.x4.shared.b16 {%0,%1,%2,%3}, [%4];"
                 : "=r"(r[0]), "=r"(r[1]), "=r"(r[2]), "=r"(r[3]) : "r"(a));
}
__device__ __forceinline__ void ldsm4t(uint32_t r[4], uint32_t a) {
    asm volatile("ldmatrix.sync.aligned.m8n8.x4.trans.shared.b16 {%0,%1,%2,%3}, [%4];"
                 : "=r"(r[0]), "=r"(r[1]), "=r"(r[2]), "=r"(r[3]) : "r"(a));
}
__device__ __forceinline__ void mma_f16(float c[4], const uint32_t a[4],
                                        const uint32_t b[2]) {
    asm volatile(
        "mma.sync.aligned.m16n8k16.row.col.f32.f16.f16.f32 "
        "{%0,%1,%2,%3}, {%4,%5,%6,%7}, {%8,%9}, {%0,%1,%2,%3};"
        : "+f"(c[0]), "+f"(c[1]), "+f"(c[2]), "+f"(c[3])
        : "r"(a[0]), "r"(a[1]), "r"(a[2]), "r"(a[3]), "r"(b[0]), "r"(b[1]));
}
__device__ __forceinline__ float ex2(float x) {
    float y;
    asm("ex2.approx.f32 %0, %1;" : "=f"(y) : "f"(x));
    return y;
}
__device__ __forceinline__ uint32_t h2ex2(uint32_t x) {
    uint32_t y;
    asm("ex2.approx.f16x2 %0, %1;" : "=r"(y) : "r"(x));
    return y;
}
__device__ __forceinline__ uint32_t hadd2(uint32_t a, uint32_t b) {
    uint32_t d;
    asm("add.f16x2 %0, %1, %2;" : "=r"(d) : "r"(a), "r"(b));
    return d;
}
__device__ __forceinline__ float2 h2f2(uint32_t h) {
    __half2 v = *reinterpret_cast<__half2*>(&h);
    return __half22float2(v);
}
__device__ __forceinline__ uint32_t fpk(float a, float b) {
    __half2 t = __floats2half2_rn(a, b);
    return *reinterpret_cast<uint32_t*>(&t);
}

// ============================================================================
// Prep: one kernel converts inputs + weights AND scans the mask.
// ============================================================================
__global__ __launch_bounds__(256) void prep_all(
    const float* __restrict__ q, const float* __restrict__ k,
    const float* __restrict__ v, const float* __restrict__ in_w,
    const float* __restrict__ out_w, const float* __restrict__ mask)
{
    const int b = blockIdx.x;
    if (b < 12288) {
        const int z = b >> 12;                 // /4096
        const float* s = (z == 0) ? q : (z == 1) ? k : v;
        const size_t i = ((size_t)(b & 4095) * 256 + threadIdx.x) * 4;
        float4 x = *(const float4*)(s + i);
        uint2 H;
        H.x = fpk(x.x, x.y);
        H.y = fpk(x.z, x.w);
        *(uint2*)(g_in + (size_t)z * NELEM + i) = H;
    } else if (b < 16384) {
        const size_t i = ((size_t)(b - 12288) * 256 + threadIdx.x) * 4;
        const size_t NW = (size_t)3 * EMB * DM;
        const float* s = (i < NW) ? (in_w + i) : (out_w + (i - NW));
        __half* d = (i < NW) ? (g_wih + i) : (g_woh + (i - NW));
        float4 x = *(const float4*)s;
        uint2 H;
        H.x = fpk(x.x, x.y);
        H.y = fpk(x.z, x.w);
        *(uint2*)d = H;
    } else {
        const size_t i = ((size_t)(b - 16384) * 256 + threadIdx.x) * 4;
        float4 x = *(const float4*)(mask + i);
        if (x.x != 0.f || x.y != 0.f || x.z != 0.f || x.w != 0.f) g_mask_nz = 1;
    }
}

__global__ void mask_flag_reset() { g_mask_nz = 0; }

// ============================================================================
// GEMM core (TN, single fp16): CTA 128x128, chunk K=32, 3-stage cp.async,
// staging issued at TOP of iteration -> single __syncthreads per chunk.
// smem/stage: A[128x32] W[128x32] fp16, row stride 80B. 8 warps = 2m x 4n.
// (round-13 config — measured best for the GEMMs)
// ============================================================================
#define GRS 80
#define S_A 0
#define S_W 10240
#define G_STAGE 20480
#define G_SMEM (3 * G_STAGE)

__device__ __forceinline__ void g_load(uint32_t sb, const __half* A,
                                       const __half* Wg,
                                       int m0, int n0, int c, int buf, int tid)
{
    const uint32_t st = sb + buf * G_STAGE;
    const int k0 = c * 32;
    #pragma unroll
    for (int i = 0; i < 2; i++) {
        const int idx = tid + i * 256;          // 0..511
        const int row = idx >> 2, cc = idx & 3;
        const uint32_t o = row * GRS + cc * 16;
        cpa(st + S_A + o, A  + (size_t)(m0 + row) * DM + k0 + cc * 8);
        cpa(st + S_W + o, Wg + (size_t)(n0 + row) * DM + k0 + cc * 8);
    }
    cp_commit();
}

__device__ __forceinline__ void gemm_core(
    const __half* __restrict__ A, const __half* __restrict__ Wg,
    int m0, int n0, uint32_t sb, float (&acc)[4][4][4])
{
    const int tid = threadIdx.x, lane = tid & 31, wid = tid >> 5;
    const int mh = wid & 1;          // 0..1 : 64-row half
    const int nq = wid >> 1;         // 0..3 : 32-col quad

    #pragma unroll
    for (int i = 0; i < 4; i++)
        #pragma unroll
        for (int j = 0; j < 4; j++)
            #pragma unroll
            for (int v = 0; v < 4; v++) acc[i][j][v] = 0.f;

    g_load(sb, A, Wg, m0, n0, 0, 0, tid);
    g_load(sb, A, Wg, m0, n0, 1, 1, tid);

    const int a_l = (mh * 64 + (lane & 15)) * GRS + ((lane >> 4) << 3) * 2;
    const int b_l = (nq * 32 + ((lane >> 4) << 3) + (lane & 7)) * GRS + (lane & 8) * 2;

    int b_rd = 0, b_wr = 2;
    #pragma unroll 1
    for (int c = 0; c < 32; c++) {
        if (c == 31) cp_wait0(); else cp_wait1();
        __syncthreads();
        if (c + 2 < 32) g_load(sb, A, Wg, m0, n0, c + 2, b_wr, tid);

        const uint32_t st = sb + b_rd * G_STAGE;
        #pragma unroll
        for (int kk = 0; kk < 2; kk++) {
            uint32_t af[4][4], bf[4][2];
            #pragma unroll
            for (int mi = 0; mi < 4; mi++)
                ldsm4(af[mi], st + S_A + a_l + mi * 16 * GRS + kk * 32);
            #pragma unroll
            for (int np = 0; np < 2; np++) {
                uint32_t t[4];
                ldsm4(t, st + S_W + b_l + np * 16 * GRS + kk * 32);
                bf[np * 2][0] = t[0]; bf[np * 2][1] = t[1];
                bf[np * 2 + 1][0] = t[2]; bf[np * 2 + 1][1] = t[3];
            }
            #pragma unroll
            for (int mi = 0; mi < 4; mi++)
                #pragma unroll
                for (int ni = 0; ni < 4; ni++)
                    mma_f16(acc[mi][ni], af[mi], bf[ni]);
        }
        b_rd = (b_rd == 2) ? 0 : b_rd + 1;
        b_wr = (b_wr == 2) ? 0 : b_wr + 1;
    }
}

// -------- QKV projection: z selects q/k/v; writes fp16 per-head -------------
__global__ __launch_bounds__(256, 2) void qkv_gemm(const float* __restrict__ bias)
{
    extern __shared__ char sm[];
    const int z = blockIdx.z;
    const __half* A  = g_in + (size_t)z * NELEM;
    const __half* Wg = g_wih + (size_t)z * EMB * DM;
    const float* bz = bias + z * EMB;

    const int m0 = blockIdx.y * 128;
    const int n0 = blockIdx.x * 128;

    float acc[4][4][4];
    gemm_core(A, Wg, m0, n0, su32(sm), acc);

    const int lane = threadIdx.x & 31, wid = threadIdx.x >> 5;
    const int mh = wid & 1, nq = wid >> 1;
    const int g = lane >> 2, t4 = lane & 3;

    __half* dst = (z == 0) ? g_qh : (z == 1) ? g_kh : g_vh;
    const float sc = (z == 0) ? (0.125f * LOG2E) : 1.0f;   // exp2-domain scores

    #pragma unroll
    for (int mi = 0; mi < 4; mi++) {
        #pragma unroll
        for (int ni = 0; ni < 4; ni++) {
            const int mrow = m0 + mh * 64 + mi * 16 + g;
            const int ncol = n0 + nq * 32 + ni * 8 + t4 * 2;
            const float b0 = __ldg(&bz[ncol]), b1 = __ldg(&bz[ncol + 1]);
            const int h = ncol >> 6, d = ncol & 63;
            #pragma unroll
            for (int rr = 0; rr < 2; rr++) {
                const int m = mrow + rr * 8;
                const int t = m >> 1, b = m & 1;
                const float v0 = (acc[mi][ni][rr * 2 + 0] + b0) * sc;
                const float v1 = (acc[mi][ni][rr * 2 + 1] + b1) * sc;
                const size_t idx = ((size_t)(b * NH + h) * T_LEN + t) * HD + d;
                *(uint32_t*)(dst + idx) = fpk(v0, v1);
            }
        }
    }
}

// -------- Output projection: C = attn(fp16) @ Wo^T + bo ---------------------
__global__ __launch_bounds__(256, 2) void out_gemm(const float* __restrict__ bias,
                                                   float* __restrict__ C)
{
    extern __shared__ char sm[];
    const int m0 = blockIdx.y * 128;
    const int n0 = blockIdx.x * 128;

    float acc[4][4][4];
    gemm_core(g_ah, g_woh, m0, n0, su32(sm), acc);

    const int lane = threadIdx.x & 31, wid = threadIdx.x >> 5;
    const int mh = wid & 1, nq = wid >> 1;
    const int g = lane >> 2, t4 = lane & 3;

    #pragma unroll
    for (int mi = 0; mi < 4; mi++) {
        #pragma unroll
        for (int ni = 0; ni < 4; ni++) {
            const int mrow = m0 + mh * 64 + mi * 16 + g;
            const int ncol = n0 + nq * 32 + ni * 8 + t4 * 2;
            const float b0 = __ldg(&bias[ncol]), b1 = __ldg(&bias[ncol + 1]);
            #pragma unroll
            for (int rr = 0; rr < 2; rr++) {
                const int m = mrow + rr * 8;
                float2 v;
                v.x = acc[mi][ni][rr * 2 + 0] + b0;
                v.y = acc[mi][ni][rr * 2 + 1] + b1;
                *(float2*)(C + (size_t)m * DM + ncol) = v;
            }
        }
    }
}

// ============================================================================
// Flash attention — EXACT round-12 configuration (measured best: 115.3 us).
// fp16 mma, f16x2 exp2 softmax, 4 warps x 32 q-rows (two m16 groups/warp),
// K/V 2-stage double-buffered, lazy (non-speculative) rescale.
// ============================================================================
#define ARS 144
#define F_Q  0
#define F_KV 18432
#define F_KVS 18432          // per stage: K 9216 + V 9216
#define F_SMEM (F_KV + 2 * F_KVS)   // 55296

__device__ __forceinline__ void f_stage_kv(uint32_t sb, size_t hbase, int it, int tid)
{
    const uint32_t st = sb + F_KV + (it & 1) * F_KVS;
    const int s0 = it * 64;
    #pragma unroll
    for (int i = 0; i < 4; i++) {
        const int idx = tid + i * 128;          // 0..511
        const int row = idx >> 3, cc = idx & 7;
        const size_t src = (hbase + s0 + row) * HD + cc * 8;
        cpa(st + row * ARS + cc * 16, g_kh + src);
        cpa(st + 9216 + row * ARS + cc * 16, g_vh + src);
    }
    cp_commit();
}

__global__ __launch_bounds__(128, 2) void flash_mma(const float* __restrict__ mask)
{
    extern __shared__ char sm[];
    const uint32_t sb = su32(sm);
    const int tid = threadIdx.x, lane = tid & 31, w = tid >> 5;   // 4 warps
    const int bh = blockIdx.y, qt = blockIdx.x;
    const int g = lane >> 2, t4 = lane & 3;
    const size_t hbase = (size_t)bh * T_LEN;
    const int mnz = g_mask_nz;

    {   // stage Q (128 rows)
        const size_t qb = (hbase + qt * 128) * HD;
        #pragma unroll
        for (int i = 0; i < 8; i++) {
            const int idx = tid + i * 128;      // 0..1023
            const int row = idx >> 3, cc = idx & 7;
            cpa(sb + F_Q + row * ARS + cc * 16, g_qh + qb + (size_t)row * HD + cc * 8);
        }
        cp_commit();
    }
    f_stage_kv(sb, hbase, 0, tid);
    f_stage_kv(sb, hbase, 1, tid);
    cp_wait2();
    __syncthreads();

    // q fragments: two m16 groups per warp (rows w*32+mi*16 .. +15)
    uint32_t qf[2][4][4];
    #pragma unroll
    for (int mi = 0; mi < 2; mi++)
        #pragma unroll
        for (int j = 0; j < 4; j++)
            ldsm4(qf[mi][j], sb + F_Q + (w * 32 + mi * 16 + (lane & 15)) * ARS +
                             (j * 16 + ((lane >> 4) << 3)) * 2);

    float oacc[2][8][4];
    #pragma unroll
    for (int mi = 0; mi < 2; mi++)
        #pragma unroll
        for (int i = 0; i < 8; i++)
            #pragma unroll
            for (int v = 0; v < 4; v++) oacc[mi][i][v] = 0.f;
    float mr[2][2] = {{-1e30f, -1e30f}, {-1e30f, -1e30f}};
    float lr[2][2] = {{0.f, 0.f}, {0.f, 0.f}};

    const int tq = qt * 128 + w * 32 + g;
    const float* mrow[2][2];
    mrow[0][0] = mask + (size_t)tq * T_LEN;
    mrow[0][1] = mrow[0][0] + (size_t)8 * T_LEN;
    mrow[1][0] = mrow[0][0] + (size_t)16 * T_LEN;
    mrow[1][1] = mrow[0][0] + (size_t)24 * T_LEN;

    #pragma unroll 1
    for (int it = 0; it < 32; it++) {
        if (it == 31) cp_wait0(); else cp_wait1();
        __syncthreads();
        const uint32_t kst = sb + F_KV + (it & 1) * F_KVS;
        const uint32_t vst = kst + 9216;

        // ---- S' = (Q*log2e/8) K^T : K fragments shared by both m-groups ----
        float sacc[2][8][4];
        #pragma unroll
        for (int mi = 0; mi < 2; mi++)
            #pragma unroll
            for (int i = 0; i < 8; i++)
                #pragma unroll
                for (int v = 0; v < 4; v++) sacc[mi][i][v] = 0.f;

        #pragma unroll
        for (int j = 0; j < 4; j++) {
            uint32_t kb[8][2];
            #pragma unroll
            for (int np = 0; np < 4; np++) {
                uint32_t t[4];
                ldsm4(t, kst + (np * 16 + ((lane >> 4) << 3) + (lane & 7)) * ARS +
                         (j * 16 + (lane & 8)) * 2);
                kb[np * 2][0] = t[0]; kb[np * 2][1] = t[1];
                kb[np * 2 + 1][0] = t[2]; kb[np * 2 + 1][1] = t[3];
            }
            #pragma unroll
            for (int mi = 0; mi < 2; mi++)
                #pragma unroll
                for (int jn = 0; jn < 8; jn++)
                    mma_f16(sacc[mi][jn], qf[mi][j], kb[jn]);
        }

        // ---- mask + online softmax (per m-group), exp2 domain ----
        const int s0 = it * 64;
        uint32_t p01[2][8], p23[2][8];
        #pragma unroll
        for (int mi = 0; mi < 2; mi++) {
            if (mnz) {
                #pragma unroll
                for (int jn = 0; jn < 8; jn++) {
                    const int sc = s0 + jn * 8 + t4 * 2;
                    float2 ma = *(const float2*)(mrow[mi][0] + sc);
                    float2 mb = *(const float2*)(mrow[mi][1] + sc);
                    sacc[mi][jn][0] = fmaf(ma.x, LOG2E, sacc[mi][jn][0]);
                    sacc[mi][jn][1] = fmaf(ma.y, LOG2E, sacc[mi][jn][1]);
                    sacc[mi][jn][2] = fmaf(mb.x, LOG2E, sacc[mi][jn][2]);
                    sacc[mi][jn][3] = fmaf(mb.y, LOG2E, sacc[mi][jn][3]);
                }
            }
            float mx0 = -1e30f, mx1 = -1e30f;
            #pragma unroll
            for (int jn = 0; jn < 8; jn++) {
                mx0 = fmaxf(mx0, fmaxf(sacc[mi][jn][0], sacc[mi][jn][1]));
                mx1 = fmaxf(mx1, fmaxf(sacc[mi][jn][2], sacc[mi][jn][3]));
            }
            mx0 = fmaxf(mx0, __shfl_xor_sync(0xffffffffu, mx0, 1));
            mx0 = fmaxf(mx0, __shfl_xor_sync(0xffffffffu, mx0, 2));
            mx1 = fmaxf(mx1, __shfl_xor_sync(0xffffffffu, mx1, 1));
            mx1 = fmaxf(mx1, __shfl_xor_sync(0xffffffffu, mx1, 2));

            if (mx0 > mr[mi][0]) {
                const float c0 = ex2(mr[mi][0] - mx0);
                mr[mi][0] = mx0;
                lr[mi][0] *= c0;
                #pragma unroll
                for (int jd = 0; jd < 8; jd++) {
                    oacc[mi][jd][0] *= c0; oacc[mi][jd][1] *= c0;
                }
            }
            if (mx1 > mr[mi][1]) {
                const float c1 = ex2(mr[mi][1] - mx1);
                mr[mi][1] = mx1;
                lr[mi][1] *= c1;
                #pragma unroll
                for (int jd = 0; jd < 8; jd++) {
                    oacc[mi][jd][2] *= c1; oacc[mi][jd][3] *= c1;
                }
            }
            #pragma unroll
            for (int jn = 0; jn < 8; jn++) {
                p01[mi][jn] = h2ex2(fpk(sacc[mi][jn][0] - mr[mi][0],
                                        sacc[mi][jn][1] - mr[mi][0]));
                p23[mi][jn] = h2ex2(fpk(sacc[mi][jn][2] - mr[mi][1],
                                        sacc[mi][jn][3] - mr[mi][1]));
            }
            #pragma unroll
            for (int jn = 0; jn < 8; jn += 2) {
                float2 f0 = h2f2(hadd2(p01[mi][jn], p01[mi][jn + 1]));
                float2 f1 = h2f2(hadd2(p23[mi][jn], p23[mi][jn + 1]));
                lr[mi][0] += f0.x + f0.y;
                lr[mi][1] += f1.x + f1.y;
            }
        }

        // ---- O += P V : V fragments shared by both m-groups ----
        #pragma unroll
        for (int js = 0; js < 4; js++) {
            uint32_t vb[8][2];
            #pragma unroll
            for (int dp = 0; dp < 4; dp++) {
                uint32_t t[4];
                ldsm4t(t, vst + (js * 16 + (lane & 15)) * ARS +
                          (dp * 16 + ((lane >> 4) << 3)) * 2);
                vb[dp * 2][0] = t[0]; vb[dp * 2][1] = t[1];
                vb[dp * 2 + 1][0] = t[2]; vb[dp * 2 + 1][1] = t[3];
            }
            #pragma unroll
            for (int mi = 0; mi < 2; mi++) {
                uint32_t pf[4];
                pf[0] = p01[mi][2 * js];
                pf[1] = p23[mi][2 * js];
                pf[2] = p01[mi][2 * js + 1];
                pf[3] = p23[mi][2 * js + 1];
                #pragma unroll
                for (int jd = 0; jd < 8; jd++)
                    mma_f16(oacc[mi][jd], pf, vb[jd]);
            }
        }
        __syncthreads();
        if (it + 2 < 32) f_stage_kv(sb, hbase, it + 2, tid);
    }

    const int b = bh >> 4, h = bh & 15;
    #pragma unroll
    for (int mi = 0; mi < 2; mi++) {
        float l0 = lr[mi][0], l1 = lr[mi][1];
        l0 += __shfl_xor_sync(0xffffffffu, l0, 1);
        l0 += __shfl_xor_sync(0xffffffffu, l0, 2);
        l1 += __shfl_xor_sync(0xffffffffu, l1, 1);
        l1 += __shfl_xor_sync(0xffffffffu, l1, 2);
        const float i0 = 1.0f / l0, i1 = 1.0f / l1;

        const int trow = tq + mi * 16;
        const size_t r0 = ((size_t)trow * BSZ + b) * EMB + h * HD;
        const size_t r1 = ((size_t)(trow + 8) * BSZ + b) * EMB + h * HD;
        #pragma unroll
        for (int jd = 0; jd < 8; jd++) {
            const int d = jd * 8 + t4 * 2;
            *(uint32_t*)(g_ah + r0 + d) = fpk(oacc[mi][jd][0] * i0,
                                              oacc[mi][jd][1] * i0);
            *(uint32_t*)(g_ah + r1 + d) = fpk(oacc[mi][jd][2] * i1,
                                              oacc[mi][jd][3] * i1);
        }
    }
}

// ============================================================================
// Launch
// ============================================================================
extern "C" void kernel_launch(void* const* d_in, const int* in_sizes, int n_in,
                              void* d_out, int out_size)
{
    const float* query  = (const float*)d_in[0];
    const float* key    = (const float*)d_in[1];
    const float* value  = (const float*)d_in[2];
    const float* mask   = (const float*)d_in[3];
    const float* in_w   = (const float*)d_in[4];
    const float* in_b   = (const float*)d_in[5];
    const float* out_w  = (const float*)d_in[6];
    const float* out_b  = (const float*)d_in[7];
    float* out = (float*)d_out;

    cudaFuncSetAttribute(qkv_gemm, cudaFuncAttributeMaxDynamicSharedMemorySize, G_SMEM);
    cudaFuncSetAttribute(out_gemm, cudaFuncAttributeMaxDynamicSharedMemorySize, G_SMEM);
    cudaFuncSetAttribute(flash_mma, cudaFuncAttributeMaxDynamicSharedMemorySize, F_SMEM);

    // 0) prep: reset flag, then convert inputs + weights + scan mask (1 kernel)
    mask_flag_reset<<<1, 1>>>();
    prep_all<<<20480, 256>>>(query, key, value, in_w, out_w, mask);

    // 1) QKV projection (fp16 mma, 128x128 tiles, 3-stage top-staged)
    qkv_gemm<<<dim3(EMB / 128, MROWS / 128, 3), 256, G_SMEM>>>(in_b);

    // 2) Attention (fp16 mma flash, round-12 config: 2-stage KV, lazy rescale)
    flash_mma<<<dim3(T_LEN / 128, BSZ * NH), 128, F_SMEM>>>(mask);

    // 3) Output projection (fp16 mma, 3-stage top-staged) -> d_out
    out_gemm<<<dim3(DM / 128, MROWS / 128), 256, G_SMEM>>>(out_b, out);
}

// round 16
// speedup vs baseline: 1.0372x; 1.0205x over previous
#include <cuda_runtime.h>
#include <cuda_fp16.h>
#include <cstdint>

#define T_LEN 2048
#define BSZ   2
#define DM    1024
#define NH    16
#define HD    64
#define EMB   1024
#define MROWS 4096
#define NELEM ((size_t)MROWS * DM)          // 4M elements per input tensor
#define LOG2E 1.4426950408889634f

// ---------------- scratch (allocation-free: device globals) ----------------
__device__ __half g_in[3 * NELEM];          // inputs fp16 (q,k,v)
__device__ __half g_wih[(size_t)3 * EMB * DM];  // in_proj_weight fp16
__device__ __half g_woh[(size_t)DM * EMB];      // out_proj_weight fp16
__device__ __half g_qh[(size_t)BSZ * NH * T_LEN * HD];  // q fp16 (scaled 1/8*log2e)
__device__ __half g_kh[(size_t)BSZ * NH * T_LEN * HD];  // k fp16
__device__ __half g_vh[(size_t)BSZ * NH * T_LEN * HD];  // v fp16
__device__ __half g_ah[NELEM];              // attn out fp16  [t*B+b][e]
__device__ int g_mask_nz;                   // 1 if mask has any nonzero
// NOTE: g_mask_nz is monotonic (set to 1 only when mask has nonzeros; device
// globals init to 0) — no reset launch needed; deterministic across replays.

// ============================ PTX helpers ===================================
__device__ __forceinline__ uint32_t su32(const void* p) {
    uint32_t a;
    asm("{ .reg .u64 t; cvta.to.shared.u64 t, %1; cvt.u32.u64 %0, t; }"
        : "=r"(a) : "l"(p));
    return a;
}
__device__ __forceinline__ void cpa(uint32_t s, const void* g) {
    asm volatile("cp.async.cg.shared.global [%0], [%1], 16;" :: "r"(s), "l"(g));
}
__device__ __forceinline__ void cp_commit() {
    asm volatile("cp.async.commit_group;" ::: "memory");
}
__device__ __forceinline__ void cp_wait0() {
    asm volatile("cp.async.wait_group 0;" ::: "memory");
}
__device__ __forceinline__ void cp_wait1() {
    asm volatile("cp.async.wait_group 1;" ::: "memory");
}
__device__ __forceinline__ void cp_wait2() {
    asm volatile("cp.async.wait_group 2;" ::: "memory");
}
__device__ __forceinline__ void ldsm4(uint32_t r[4], uint32_t a) {
    asm volatile("ldmatrix.sync.aligned.m8n8.x4.shared.b16 {%0,%1,%2,%3}, [%4];"
                 : "=r"(r[0]), "=r"(r[1]), "=r"(r[2]), "=r"(r[3]) : "r"(a));
}
__device__ __forceinline__ void ldsm4t(uint32_t r[4], uint32_t a) {
    asm volatile("ldmatrix.sync.aligned.m8n8.x4.trans.shared.b16 {%0,%1,%2,%3}, [%4];"
                 : "=r"(r[0]), "=r"(r[1]), "=r"(r[2]), "=r"(r[3]) : "r"(a));
}
__device__ __forceinline__ void mma_f16(float c[4], const uint32_t a[4],
                                        const uint32_t b[2]) {
    asm volatile(
        "mma.sync.aligned.m16n8k16.row.col.f32.f16.f16.f32 "
        "{%0,%1,%2,%3}, {%4,%5,%6,%7}, {%8,%9}, {%0,%1,%2,%3};"
        : "+f"(c[0]), "+f"(c[1]), "+f"(c[2]), "+f"(c[3])
        : "r"(a[0]), "r"(a[1]), "r"(a[2]), "r"(a[3]), "r"(b[0]), "r"(b[1]));
}
__device__ __forceinline__ float ex2(float x) {
    float y;
    asm("ex2.approx.f32 %0, %1;" : "=f"(y) : "f"(x));
    return y;
}
__device__ __forceinline__ uint32_t h2ex2(uint32_t x) {
    uint32_t y;
    asm("ex2.approx.f16x2 %0, %1;" : "=r"(y) : "r"(x));
    return y;
}
__device__ __forceinline__ uint32_t hadd2(uint32_t a, uint32_t b) {
    uint32_t d;
    asm("add.f16x2 %0, %1, %2;" : "=r"(d) : "r"(a), "r"(b));
    return d;
}
__device__ __forceinline__ float2 h2f2(uint32_t h) {
    __half2 v = *reinterpret_cast<__half2*>(&h);
    return __half22float2(v);
}
__device__ __forceinline__ uint32_t fpk(float a, float b) {
    __half2 t = __floats2half2_rn(a, b);
    return *reinterpret_cast<uint32_t*>(&t);
}

// ============================================================================
// Prep: one kernel converts inputs + weights AND scans the mask.
// ============================================================================
__global__ __launch_bounds__(256) void prep_all(
    const float* __restrict__ q, const float* __restrict__ k,
    const float* __restrict__ v, const float* __restrict__ in_w,
    const float* __restrict__ out_w, const float* __restrict__ mask)
{
    const int b = blockIdx.x;
    if (b < 12288) {
        const int z = b >> 12;                 // /4096
        const float* s = (z == 0) ? q : (z == 1) ? k : v;
        const size_t i = ((size_t)(b & 4095) * 256 + threadIdx.x) * 4;
        float4 x = *(const float4*)(s + i);
        uint2 H;
        H.x = fpk(x.x, x.y);
        H.y = fpk(x.z, x.w);
        *(uint2*)(g_in + (size_t)z * NELEM + i) = H;
    } else if (b < 16384) {
        const size_t i = ((size_t)(b - 12288) * 256 + threadIdx.x) * 4;
        const size_t NW = (size_t)3 * EMB * DM;
        const float* s = (i < NW) ? (in_w + i) : (out_w + (i - NW));
        __half* d = (i < NW) ? (g_wih + i) : (g_woh + (i - NW));
        float4 x = *(const float4*)s;
        uint2 H;
        H.x = fpk(x.x, x.y);
        H.y = fpk(x.z, x.w);
        *(uint2*)d = H;
    } else {
        const size_t i = ((size_t)(b - 16384) * 256 + threadIdx.x) * 4;
        float4 x = *(const float4*)(mask + i);
        if (x.x != 0.f || x.y != 0.f || x.z != 0.f || x.w != 0.f) g_mask_nz = 1;
    }
}

// ============================================================================
// GEMM core (TN, single fp16): CTA 128x128, chunk K=32, 3-stage cp.async,
// staging issued at TOP of iteration -> single __syncthreads per chunk.
// (round-13 config — measured best for the GEMMs)
// ============================================================================
#define GRS 80
#define S_A 0
#define S_W 10240
#define G_STAGE 20480
#define G_SMEM (3 * G_STAGE)

__device__ __forceinline__ void g_load(uint32_t sb, const __half* A,
                                       const __half* Wg,
                                       int m0, int n0, int c, int buf, int tid)
{
    const uint32_t st = sb + buf * G_STAGE;
    const int k0 = c * 32;
    #pragma unroll
    for (int i = 0; i < 2; i++) {
        const int idx = tid + i * 256;          // 0..511
        const int row = idx >> 2, cc = idx & 3;
        const uint32_t o = row * GRS + cc * 16;
        cpa(st + S_A + o, A  + (size_t)(m0 + row) * DM + k0 + cc * 8);
        cpa(st + S_W + o, Wg + (size_t)(n0 + row) * DM + k0 + cc * 8);
    }
    cp_commit();
}

__device__ __forceinline__ void gemm_core(
    const __half* __restrict__ A, const __half* __restrict__ Wg,
    int m0, int n0, uint32_t sb, float (&acc)[4][4][4])
{
    const int tid = threadIdx.x, lane = tid & 31, wid = tid >> 5;
    const int mh = wid & 1;          // 0..1 : 64-row half
    const int nq = wid >> 1;         // 0..3 : 32-col quad

    #pragma unroll
    for (int i = 0; i < 4; i++)
        #pragma unroll
        for (int j = 0; j < 4; j++)
            #pragma unroll
            for (int v = 0; v < 4; v++) acc[i][j][v] = 0.f;

    g_load(sb, A, Wg, m0, n0, 0, 0, tid);
    g_load(sb, A, Wg, m0, n0, 1, 1, tid);

    const int a_l = (mh * 64 + (lane & 15)) * GRS + ((lane >> 4) << 3) * 2;
    const int b_l = (nq * 32 + ((lane >> 4) << 3) + (lane & 7)) * GRS + (lane & 8) * 2;

    int b_rd = 0, b_wr = 2;
    #pragma unroll 1
    for (int c = 0; c < 32; c++) {
        if (c == 31) cp_wait0(); else cp_wait1();
        __syncthreads();
        if (c + 2 < 32) g_load(sb, A, Wg, m0, n0, c + 2, b_wr, tid);

        const uint32_t st = sb + b_rd * G_STAGE;
        #pragma unroll
        for (int kk = 0; kk < 2; kk++) {
            uint32_t af[4][4], bf[4][2];
            #pragma unroll
            for (int mi = 0; mi < 4; mi++)
                ldsm4(af[mi], st + S_A + a_l + mi * 16 * GRS + kk * 32);
            #pragma unroll
            for (int np = 0; np < 2; np++) {
                uint32_t t[4];
                ldsm4(t, st + S_W + b_l + np * 16 * GRS + kk * 32);
                bf[np * 2][0] = t[0]; bf[np * 2][1] = t[1];
                bf[np * 2 + 1][0] = t[2]; bf[np * 2 + 1][1] = t[3];
            }
            #pragma unroll
            for (int mi = 0; mi < 4; mi++)
                #pragma unroll
                for (int ni = 0; ni < 4; ni++)
                    mma_f16(acc[mi][ni], af[mi], bf[ni]);
        }
        b_rd = (b_rd == 2) ? 0 : b_rd + 1;
        b_wr = (b_wr == 2) ? 0 : b_wr + 1;
    }
}

// -------- QKV projection: z selects q/k/v; writes fp16 per-head -------------
__global__ __launch_bounds__(256, 2) void qkv_gemm(const float* __restrict__ bias)
{
    extern __shared__ char sm[];
    const int z = blockIdx.z;
    const __half* A  = g_in + (size_t)z * NELEM;
    const __half* Wg = g_wih + (size_t)z * EMB * DM;
    const float* bz = bias + z * EMB;

    const int m0 = blockIdx.y * 128;
    const int n0 = blockIdx.x * 128;

    float acc[4][4][4];
    gemm_core(A, Wg, m0, n0, su32(sm), acc);

    const int lane = threadIdx.x & 31, wid = threadIdx.x >> 5;
    const int mh = wid & 1, nq = wid >> 1;
    const int g = lane >> 2, t4 = lane & 3;

    __half* dst = (z == 0) ? g_qh : (z == 1) ? g_kh : g_vh;
    const float sc = (z == 0) ? (0.125f * LOG2E) : 1.0f;   // exp2-domain scores

    #pragma unroll
    for (int mi = 0; mi < 4; mi++) {
        #pragma unroll
        for (int ni = 0; ni < 4; ni++) {
            const int mrow = m0 + mh * 64 + mi * 16 + g;
            const int ncol = n0 + nq * 32 + ni * 8 + t4 * 2;
            const float b0 = __ldg(&bz[ncol]), b1 = __ldg(&bz[ncol + 1]);
            const int h = ncol >> 6, d = ncol & 63;
            #pragma unroll
            for (int rr = 0; rr < 2; rr++) {
                const int m = mrow + rr * 8;
                const int t = m >> 1, b = m & 1;
                const float v0 = (acc[mi][ni][rr * 2 + 0] + b0) * sc;
                const float v1 = (acc[mi][ni][rr * 2 + 1] + b1) * sc;
                const size_t idx = ((size_t)(b * NH + h) * T_LEN + t) * HD + d;
                *(uint32_t*)(dst + idx) = fpk(v0, v1);
            }
        }
    }
}

// -------- Output projection: C = attn(fp16) @ Wo^T + bo ---------------------
__global__ __launch_bounds__(256, 2) void out_gemm(const float* __restrict__ bias,
                                                   float* __restrict__ C)
{
    extern __shared__ char sm[];
    const int m0 = blockIdx.y * 128;
    const int n0 = blockIdx.x * 128;

    float acc[4][4][4];
    gemm_core(g_ah, g_woh, m0, n0, su32(sm), acc);

    const int lane = threadIdx.x & 31, wid = threadIdx.x >> 5;
    const int mh = wid & 1, nq = wid >> 1;
    const int g = lane >> 2, t4 = lane & 3;

    #pragma unroll
    for (int mi = 0; mi < 4; mi++) {
        #pragma unroll
        for (int ni = 0; ni < 4; ni++) {
            const int mrow = m0 + mh * 64 + mi * 16 + g;
            const int ncol = n0 + nq * 32 + ni * 8 + t4 * 2;
            const float b0 = __ldg(&bias[ncol]), b1 = __ldg(&bias[ncol + 1]);
            #pragma unroll
            for (int rr = 0; rr < 2; rr++) {
                const int m = mrow + rr * 8;
                float2 v;
                v.x = acc[mi][ni][rr * 2 + 0] + b0;
                v.y = acc[mi][ni][rr * 2 + 1] + b1;
                *(float2*)(C + (size_t)m * DM + ncol) = v;
            }
        }
    }
}

// ============================================================================
// Flash attention: round-12 math (fp16 mma, f16x2 exp2, 4 warps x 32 q-rows,
// lazy rescale) with NEW 3-stage KV + single TOP barrier + BOTTOM staging.
// l-accumulation moved after PV mma issue.
// ============================================================================
#define ARS 144
#define F_Q  0
#define F_KV 18432
#define F_KVS 18432          // per stage: K 9216 + V 9216
#define F_SMEM (F_KV + 3 * F_KVS)   // 73728

__device__ __forceinline__ void f_stage_kv(uint32_t sb, size_t hbase, int it,
                                           int buf, int tid)
{
    const uint32_t st = sb + F_KV + buf * F_KVS;
    const int s0 = it * 64;
    #pragma unroll
    for (int i = 0; i < 4; i++) {
        const int idx = tid + i * 128;          // 0..511
        const int row = idx >> 3, cc = idx & 7;
        const size_t src = (hbase + s0 + row) * HD + cc * 8;
        cpa(st + row * ARS + cc * 16, g_kh + src);
        cpa(st + 9216 + row * ARS + cc * 16, g_vh + src);
    }
    cp_commit();
}

__global__ __launch_bounds__(128, 2) void flash_mma(const float* __restrict__ mask)
{
    extern __shared__ char sm[];
    const uint32_t sb = su32(sm);
    const int tid = threadIdx.x, lane = tid & 31, w = tid >> 5;   // 4 warps
    const int bh = blockIdx.y, qt = blockIdx.x;
    const int g = lane >> 2, t4 = lane & 3;
    const size_t hbase = (size_t)bh * T_LEN;
    const int mnz = g_mask_nz;

    {   // stage Q (128 rows)
        const size_t qb = (hbase + qt * 128) * HD;
        #pragma unroll
        for (int i = 0; i < 8; i++) {
            const int idx = tid + i * 128;      // 0..1023
            const int row = idx >> 3, cc = idx & 7;
            cpa(sb + F_Q + row * ARS + cc * 16, g_qh + qb + (size_t)row * HD + cc * 8);
        }
        cp_commit();
    }
    f_stage_kv(sb, hbase, 0, 0, tid);
    f_stage_kv(sb, hbase, 1, 1, tid);
    cp_wait2();                                 // Q complete
    __syncthreads();

    uint32_t qf[2][4][4];
    #pragma unroll
    for (int mi = 0; mi < 2; mi++)
        #pragma unroll
        for (int j = 0; j < 4; j++)
            ldsm4(qf[mi][j], sb + F_Q + (w * 32 + mi * 16 + (lane & 15)) * ARS +
                             (j * 16 + ((lane >> 4) << 3)) * 2);

    float oacc[2][8][4];
    #pragma unroll
    for (int mi = 0; mi < 2; mi++)
        #pragma unroll
        for (int i = 0; i < 8; i++)
            #pragma unroll
            for (int v = 0; v < 4; v++) oacc[mi][i][v] = 0.f;
    float mr[2][2] = {{-1e30f, -1e30f}, {-1e30f, -1e30f}};
    float lr[2][2] = {{0.f, 0.f}, {0.f, 0.f}};

    const int tq = qt * 128 + w * 32 + g;
    const float* mrow[2][2];
    mrow[0][0] = mask + (size_t)tq * T_LEN;
    mrow[0][1] = mrow[0][0] + (size_t)8 * T_LEN;
    mrow[1][0] = mrow[0][0] + (size_t)16 * T_LEN;
    mrow[1][1] = mrow[0][0] + (size_t)24 * T_LEN;

    int b_rd = 0, b_wr = 2;
    #pragma unroll 1
    for (int it = 0; it < 32; it++) {
        if (it == 31) cp_wait0(); else cp_wait1();
        __syncthreads();                        // single barrier per iteration

        const uint32_t kst = sb + F_KV + b_rd * F_KVS;
        const uint32_t vst = kst + 9216;

        // ---- S' = (Q*log2e/8) K^T : K fragments shared by both m-groups ----
        float sacc[2][8][4];
        #pragma unroll
        for (int mi = 0; mi < 2; mi++)
            #pragma unroll
            for (int i = 0; i < 8; i++)
                #pragma unroll
                for (int v = 0; v < 4; v++) sacc[mi][i][v] = 0.f;

        #pragma unroll
        for (int j = 0; j < 4; j++) {
            uint32_t kb[8][2];
            #pragma unroll
            for (int np = 0; np < 4; np++) {
                uint32_t t[4];
                ldsm4(t, kst + (np * 16 + ((lane >> 4) << 3) + (lane & 7)) * ARS +
                         (j * 16 + (lane & 8)) * 2);
                kb[np * 2][0] = t[0]; kb[np * 2][1] = t[1];
                kb[np * 2 + 1][0] = t[2]; kb[np * 2 + 1][1] = t[3];
            }
            #pragma unroll
            for (int mi = 0; mi < 2; mi++)
                #pragma unroll
                for (int jn = 0; jn < 8; jn++)
                    mma_f16(sacc[mi][jn], qf[mi][j], kb[jn]);
        }

        // ---- mask + online softmax (per m-group), exp2 domain ----
        const int s0 = it * 64;
        uint32_t p01[2][8], p23[2][8];
        #pragma unroll
        for (int mi = 0; mi < 2; mi++) {
            if (mnz) {
                #pragma unroll
                for (int jn = 0; jn < 8; jn++) {
                    const int sc = s0 + jn * 8 + t4 * 2;
                    float2 ma = *(const float2*)(mrow[mi][0] + sc);
                    float2 mb = *(const float2*)(mrow[mi][1] + sc);
                    sacc[mi][jn][0] = fmaf(ma.x, LOG2E, sacc[mi][jn][0]);
                    sacc[mi][jn][1] = fmaf(ma.y, LOG2E, sacc[mi][jn][1]);
                    sacc[mi][jn][2] = fmaf(mb.x, LOG2E, sacc[mi][jn][2]);
                    sacc[mi][jn][3] = fmaf(mb.y, LOG2E, sacc[mi][jn][3]);
                }
            }
            float mx0 = -1e30f, mx1 = -1e30f;
            #pragma unroll
            for (int jn = 0; jn < 8; jn++) {
                mx0 = fmaxf(mx0, fmaxf(sacc[mi][jn][0], sacc[mi][jn][1]));
                mx1 = fmaxf(mx1, fmaxf(sacc[mi][jn][2], sacc[mi][jn][3]));
            }
            mx0 = fmaxf(mx0, __shfl_xor_sync(0xffffffffu, mx0, 1));
            mx0 = fmaxf(mx0, __shfl_xor_sync(0xffffffffu, mx0, 2));
            mx1 = fmaxf(mx1, __shfl_xor_sync(0xffffffffu, mx1, 1));
            mx1 = fmaxf(mx1, __shfl_xor_sync(0xffffffffu, mx1, 2));

            if (mx0 > mr[mi][0]) {
                const float c0 = ex2(mr[mi][0] - mx0);
                mr[mi][0] = mx0;
                lr[mi][0] *= c0;
                #pragma unroll
                for (int jd = 0; jd < 8; jd++) {
                    oacc[mi][jd][0] *= c0; oacc[mi][jd][1] *= c0;
                }
            }
            if (mx1 > mr[mi][1]) {
                const float c1 = ex2(mr[mi][1] - mx1);
                mr[mi][1] = mx1;
                lr[mi][1] *= c1;
                #pragma unroll
                for (int jd = 0; jd < 8; jd++) {
                    oacc[mi][jd][2] *= c1; oacc[mi][jd][3] *= c1;
                }
            }
            #pragma unroll
            for (int jn = 0; jn < 8; jn++) {
                p01[mi][jn] = h2ex2(fpk(sacc[mi][jn][0] - mr[mi][0],
                                        sacc[mi][jn][1] - mr[mi][0]));
                p23[mi][jn] = h2ex2(fpk(sacc[mi][jn][2] - mr[mi][1],
                                        sacc[mi][jn][3] - mr[mi][1]));
            }
        }

        // ---- O += P V : V fragments shared by both m-groups ----
        #pragma unroll
        for (int js = 0; js < 4; js++) {
            uint32_t vb[8][2];
            #pragma unroll
            for (int dp = 0; dp < 4; dp++) {
                uint32_t t[4];
                ldsm4t(t, vst + (js * 16 + (lane & 15)) * ARS +
                          (dp * 16 + ((lane >> 4) << 3)) * 2);
                vb[dp * 2][0] = t[0]; vb[dp * 2][1] = t[1];
                vb[dp * 2 + 1][0] = t[2]; vb[dp * 2 + 1][1] = t[3];
            }
            #pragma unroll
            for (int mi = 0; mi < 2; mi++) {
                uint32_t pf[4];
                pf[0] = p01[mi][2 * js];
                pf[1] = p23[mi][2 * js];
                pf[2] = p01[mi][2 * js + 1];
                pf[3] = p23[mi][2 * js + 1];
                #pragma unroll
                for (int jd = 0; jd < 8; jd++)
                    mma_f16(oacc[mi][jd], pf, vb[jd]);
            }
        }

        // ---- l accumulation (after PV issue; independent of mma results) ----
        #pragma unroll
        for (int mi = 0; mi < 2; mi++) {
            #pragma unroll
            for (int jn = 0; jn < 8; jn += 2) {
                float2 f0 = h2f2(hadd2(p01[mi][jn], p01[mi][jn + 1]));
                float2 f1 = h2f2(hadd2(p23[mi][jn], p23[mi][jn + 1]));
                lr[mi][0] += f0.x + f0.y;
                lr[mi][1] += f1.x + f1.y;
            }
        }

        // ---- bottom staging into buffer (it+2)%3 (safe: its readers were
        //      in iteration it-1, all past this iteration's top barrier) ----
        if (it + 2 < 32) f_stage_kv(sb, hbase, it + 2, b_wr, tid);
        b_rd = (b_rd == 2) ? 0 : b_rd + 1;
        b_wr = (b_wr == 2) ? 0 : b_wr + 1;
    }

    const int b = bh >> 4, h = bh & 15;
    #pragma unroll
    for (int mi = 0; mi < 2; mi++) {
        float l0 = lr[mi][0], l1 = lr[mi][1];
        l0 += __shfl_xor_sync(0xffffffffu, l0, 1);
        l0 += __shfl_xor_sync(0xffffffffu, l0, 2);
        l1 += __shfl_xor_sync(0xffffffffu, l1, 1);
        l1 += __shfl_xor_sync(0xffffffffu, l1, 2);
        const float i0 = 1.0f / l0, i1 = 1.0f / l1;

        const int trow = tq + mi * 16;
        const size_t r0 = ((size_t)trow * BSZ + b) * EMB + h * HD;
        const size_t r1 = ((size_t)(trow + 8) * BSZ + b) * EMB + h * HD;
        #pragma unroll
        for (int jd = 0; jd < 8; jd++) {
            const int d = jd * 8 + t4 * 2;
            *(uint32_t*)(g_ah + r0 + d) = fpk(oacc[mi][jd][0] * i0,
                                              oacc[mi][jd][1] * i0);
            *(uint32_t*)(g_ah + r1 + d) = fpk(oacc[mi][jd][2] * i1,
                                              oacc[mi][jd][3] * i1);
        }
    }
}

// ============================================================================
// Launch
// ============================================================================
extern "C" void kernel_launch(void* const* d_in, const int* in_sizes, int n_in,
                              void* d_out, int out_size)
{
    const float* query  = (const float*)d_in[0];
    const float* key    = (const float*)d_in[1];
    const float* value  = (const float*)d_in[2];
    const float* mask   = (const float*)d_in[3];
    const float* in_w   = (const float*)d_in[4];
    const float* in_b   = (const float*)d_in[5];
    const float* out_w  = (const float*)d_in[6];
    const float* out_b  = (const float*)d_in[7];
    float* out = (float*)d_out;

    cudaFuncSetAttribute(qkv_gemm, cudaFuncAttributeMaxDynamicSharedMemorySize, G_SMEM);
    cudaFuncSetAttribute(out_gemm, cudaFuncAttributeMaxDynamicSharedMemorySize, G_SMEM);
    cudaFuncSetAttribute(flash_mma, cudaFuncAttributeMaxDynamicSharedMemorySize, F_SMEM);

    // 0) prep: convert inputs + weights + scan mask (monotonic flag, no reset)
    prep_all<<<20480, 256>>>(query, key, value, in_w, out_w, mask);

    // 1) QKV projection (fp16 mma, 128x128 tiles, 3-stage top-staged)
    qkv_gemm<<<dim3(EMB / 128, MROWS / 128, 3), 256, G_SMEM>>>(in_b);

    // 2) Attention (fp16 mma flash, 3-stage KV, single barrier, bottom-staged)
    flash_mma<<<dim3(T_LEN / 128, BSZ * NH), 128, F_SMEM>>>(mask);

    // 3) Output projection (fp16 mma, 3-stage top-staged) -> d_out
    out_gemm<<<dim3(DM / 128, MROWS / 128), 256, G_SMEM>>>(out_b, out);
}

// round 17
// speedup vs baseline: 1.0533x; 1.0156x over previous
#include <cuda_runtime.h>
#include <cuda_fp16.h>
#include <cstdint>

#define T_LEN 2048
#define BSZ   2
#define DM    1024
#define NH    16
#define HD    64
#define EMB   1024
#define MROWS 4096
#define NELEM ((size_t)MROWS * DM)          // 4M elements per input tensor
#define LOG2E 1.4426950408889634f

// ---------------- scratch (allocation-free: device globals) ----------------
__device__ __half g_in[3 * NELEM];          // inputs fp16 (q,k,v)
__device__ __half g_wih[(size_t)3 * EMB * DM];  // in_proj_weight fp16
__device__ __half g_woh[(size_t)DM * EMB];      // out_proj_weight fp16
__device__ __half g_qh[(size_t)BSZ * NH * T_LEN * HD];  // q fp16 (scaled 1/8*log2e)
__device__ __half g_kh[(size_t)BSZ * NH * T_LEN * HD];  // k fp16
__device__ __half g_vh[(size_t)BSZ * NH * T_LEN * HD];  // v fp16
__device__ __half g_ah[NELEM];              // attn out fp16  [t*B+b][e]
__device__ int g_mask_nz;                   // 1 if mask has any nonzero (monotonic)

// ============================ PTX helpers ===================================
__device__ __forceinline__ uint32_t su32(const void* p) {
    uint32_t a;
    asm("{ .reg .u64 t; cvta.to.shared.u64 t, %1; cvt.u32.u64 %0, t; }"
        : "=r"(a) : "l"(p));
    return a;
}
__device__ __forceinline__ void cpa(uint32_t s, const void* g) {
    asm volatile("cp.async.cg.shared.global [%0], [%1], 16;" :: "r"(s), "l"(g));
}
__device__ __forceinline__ void cp_commit() {
    asm volatile("cp.async.commit_group;" ::: "memory");
}
__device__ __forceinline__ void cp_wait0() {
    asm volatile("cp.async.wait_group 0;" ::: "memory");
}
__device__ __forceinline__ void cp_wait1() {
    asm volatile("cp.async.wait_group 1;" ::: "memory");
}
__device__ __forceinline__ void cp_wait2() {
    asm volatile("cp.async.wait_group 2;" ::: "memory");
}
__device__ __forceinline__ void ldsm4(uint32_t r[4], uint32_t a) {
    asm volatile("ldmatrix.sync.aligned.m8n8.x4.shared.b16 {%0,%1,%2,%3}, [%4];"
                 : "=r"(r[0]), "=r"(r[1]), "=r"(r[2]), "=r"(r[3]) : "r"(a));
}
__device__ __forceinline__ void ldsm4t(uint32_t r[4], uint32_t a) {
    asm volatile("ldmatrix.sync.aligned.m8n8.x4.trans.shared.b16 {%0,%1,%2,%3}, [%4];"
                 : "=r"(r[0]), "=r"(r[1]), "=r"(r[2]), "=r"(r[3]) : "r"(a));
}
__device__ __forceinline__ void mma_f16(float c[4], const uint32_t a[4],
                                        const uint32_t b[2]) {
    asm volatile(
        "mma.sync.aligned.m16n8k16.row.col.f32.f16.f16.f32 "
        "{%0,%1,%2,%3}, {%4,%5,%6,%7}, {%8,%9}, {%0,%1,%2,%3};"
        : "+f"(c[0]), "+f"(c[1]), "+f"(c[2]), "+f"(c[3])
        : "r"(a[0]), "r"(a[1]), "r"(a[2]), "r"(a[3]), "r"(b[0]), "r"(b[1]));
}
__device__ __forceinline__ float ex2(float x) {
    float y;
    asm("ex2.approx.f32 %0, %1;" : "=f"(y) : "f"(x));
    return y;
}
__device__ __forceinline__ uint32_t h2ex2(uint32_t x) {
    uint32_t y;
    asm("ex2.approx.f16x2 %0, %1;" : "=r"(y) : "r"(x));
    return y;
}
__device__ __forceinline__ uint32_t hadd2(uint32_t a, uint32_t b) {
    uint32_t d;
    asm("add.f16x2 %0, %1, %2;" : "=r"(d) : "r"(a), "r"(b));
    return d;
}
__device__ __forceinline__ float2 h2f2(uint32_t h) {
    __half2 v = *reinterpret_cast<__half2*>(&h);
    return __half22float2(v);
}
__device__ __forceinline__ uint32_t fpk(float a, float b) {
    __half2 t = __floats2half2_rn(a, b);
    return *reinterpret_cast<uint32_t*>(&t);
}

// ============================================================================
// Prep: one kernel converts inputs + weights AND scans the mask.
// ============================================================================
__global__ __launch_bounds__(256) void prep_all(
    const float* __restrict__ q, const float* __restrict__ k,
    const float* __restrict__ v, const float* __restrict__ in_w,
    const float* __restrict__ out_w, const float* __restrict__ mask)
{
    const int b = blockIdx.x;
    if (b < 12288) {
        const int z = b >> 12;                 // /4096
        const float* s = (z == 0) ? q : (z == 1) ? k : v;
        const size_t i = ((size_t)(b & 4095) * 256 + threadIdx.x) * 4;
        float4 x = *(const float4*)(s + i);
        uint2 H;
        H.x = fpk(x.x, x.y);
        H.y = fpk(x.z, x.w);
        *(uint2*)(g_in + (size_t)z * NELEM + i) = H;
    } else if (b < 16384) {
        const size_t i = ((size_t)(b - 12288) * 256 + threadIdx.x) * 4;
        const size_t NW = (size_t)3 * EMB * DM;
        const float* s = (i < NW) ? (in_w + i) : (out_w + (i - NW));
        __half* d = (i < NW) ? (g_wih + i) : (g_woh + (i - NW));
        float4 x = *(const float4*)s;
        uint2 H;
        H.x = fpk(x.x, x.y);
        H.y = fpk(x.z, x.w);
        *(uint2*)d = H;
    } else {
        const size_t i = ((size_t)(b - 16384) * 256 + threadIdx.x) * 4;
        float4 x = *(const float4*)(mask + i);
        if (x.x != 0.f || x.y != 0.f || x.z != 0.f || x.w != 0.f) g_mask_nz = 1;
    }
}

// ============================================================================
// GEMM core (TN, single fp16): CTA 128x128, chunk K=32, 3-stage cp.async,
// staging issued at TOP of iteration -> single __syncthreads per chunk.
// ============================================================================
#define GRS 80
#define S_A 0
#define S_W 10240
#define G_STAGE 20480
#define G_SMEM (3 * G_STAGE)

__device__ __forceinline__ void g_load(uint32_t sb, const __half* A,
                                       const __half* Wg,
                                       int m0, int n0, int c, int buf, int tid)
{
    const uint32_t st = sb + buf * G_STAGE;
    const int k0 = c * 32;
    #pragma unroll
    for (int i = 0; i < 2; i++) {
        const int idx = tid + i * 256;          // 0..511
        const int row = idx >> 2, cc = idx & 3;
        const uint32_t o = row * GRS + cc * 16;
        cpa(st + S_A + o, A  + (size_t)(m0 + row) * DM + k0 + cc * 8);
        cpa(st + S_W + o, Wg + (size_t)(n0 + row) * DM + k0 + cc * 8);
    }
    cp_commit();
}

__device__ __forceinline__ void gemm_core(
    const __half* __restrict__ A, const __half* __restrict__ Wg,
    int m0, int n0, uint32_t sb, float (&acc)[4][4][4])
{
    const int tid = threadIdx.x, lane = tid & 31, wid = tid >> 5;
    const int mh = wid & 1;          // 0..1 : 64-row half
    const int nq = wid >> 1;         // 0..3 : 32-col quad

    #pragma unroll
    for (int i = 0; i < 4; i++)
        #pragma unroll
        for (int j = 0; j < 4; j++)
            #pragma unroll
            for (int v = 0; v < 4; v++) acc[i][j][v] = 0.f;

    g_load(sb, A, Wg, m0, n0, 0, 0, tid);
    g_load(sb, A, Wg, m0, n0, 1, 1, tid);

    const int a_l = (mh * 64 + (lane & 15)) * GRS + ((lane >> 4) << 3) * 2;
    const int b_l = (nq * 32 + ((lane >> 4) << 3) + (lane & 7)) * GRS + (lane & 8) * 2;

    int b_rd = 0, b_wr = 2;
    #pragma unroll 1
    for (int c = 0; c < 32; c++) {
        if (c == 31) cp_wait0(); else cp_wait1();
        __syncthreads();
        if (c + 2 < 32) g_load(sb, A, Wg, m0, n0, c + 2, b_wr, tid);

        const uint32_t st = sb + b_rd * G_STAGE;
        #pragma unroll
        for (int kk = 0; kk < 2; kk++) {
            uint32_t af[4][4], bf[4][2];
            #pragma unroll
            for (int mi = 0; mi < 4; mi++)
                ldsm4(af[mi], st + S_A + a_l + mi * 16 * GRS + kk * 32);
            #pragma unroll
            for (int np = 0; np < 2; np++) {
                uint32_t t[4];
                ldsm4(t, st + S_W + b_l + np * 16 * GRS + kk * 32);
                bf[np * 2][0] = t[0]; bf[np * 2][1] = t[1];
                bf[np * 2 + 1][0] = t[2]; bf[np * 2 + 1][1] = t[3];
            }
            #pragma unroll
            for (int mi = 0; mi < 4; mi++)
                #pragma unroll
                for (int ni = 0; ni < 4; ni++)
                    mma_f16(acc[mi][ni], af[mi], bf[ni]);
        }
        b_rd = (b_rd == 2) ? 0 : b_rd + 1;
        b_wr = (b_wr == 2) ? 0 : b_wr + 1;
    }
}

// -------- QKV projection: z selects q/k/v; writes fp16 per-head -------------
__global__ __launch_bounds__(256, 2) void qkv_gemm(const float* __restrict__ bias)
{
    extern __shared__ char sm[];
    const int z = blockIdx.z;
    const __half* A  = g_in + (size_t)z * NELEM;
    const __half* Wg = g_wih + (size_t)z * EMB * DM;
    const float* bz = bias + z * EMB;

    const int m0 = blockIdx.y * 128;
    const int n0 = blockIdx.x * 128;

    float acc[4][4][4];
    gemm_core(A, Wg, m0, n0, su32(sm), acc);

    const int lane = threadIdx.x & 31, wid = threadIdx.x >> 5;
    const int mh = wid & 1, nq = wid >> 1;
    const int g = lane >> 2, t4 = lane & 3;

    __half* dst = (z == 0) ? g_qh : (z == 1) ? g_kh : g_vh;
    const float sc = (z == 0) ? (0.125f * LOG2E) : 1.0f;

    #pragma unroll
    for (int mi = 0; mi < 4; mi++) {
        #pragma unroll
        for (int ni = 0; ni < 4; ni++) {
            const int mrow = m0 + mh * 64 + mi * 16 + g;
            const int ncol = n0 + nq * 32 + ni * 8 + t4 * 2;
            const float b0 = __ldg(&bz[ncol]), b1 = __ldg(&bz[ncol + 1]);
            const int h = ncol >> 6, d = ncol & 63;
            #pragma unroll
            for (int rr = 0; rr < 2; rr++) {
                const int m = mrow + rr * 8;
                const int t = m >> 1, b = m & 1;
                const float v0 = (acc[mi][ni][rr * 2 + 0] + b0) * sc;
                const float v1 = (acc[mi][ni][rr * 2 + 1] + b1) * sc;
                const size_t idx = ((size_t)(b * NH + h) * T_LEN + t) * HD + d;
                *(uint32_t*)(dst + idx) = fpk(v0, v1);
            }
        }
    }
}

// -------- Output projection: C = attn(fp16) @ Wo^T + bo ---------------------
__global__ __launch_bounds__(256, 2) void out_gemm(const float* __restrict__ bias,
                                                   float* __restrict__ C)
{
    extern __shared__ char sm[];
    const int m0 = blockIdx.y * 128;
    const int n0 = blockIdx.x * 128;

    float acc[4][4][4];
    gemm_core(g_ah, g_woh, m0, n0, su32(sm), acc);

    const int lane = threadIdx.x & 31, wid = threadIdx.x >> 5;
    const int mh = wid & 1, nq = wid >> 1;
    const int g = lane >> 2, t4 = lane & 3;

    #pragma unroll
    for (int mi = 0; mi < 4; mi++) {
        #pragma unroll
        for (int ni = 0; ni < 4; ni++) {
            const int mrow = m0 + mh * 64 + mi * 16 + g;
            const int ncol = n0 + nq * 32 + ni * 8 + t4 * 2;
            const float b0 = __ldg(&bias[ncol]), b1 = __ldg(&bias[ncol + 1]);
            #pragma unroll
            for (int rr = 0; rr < 2; rr++) {
                const int m = mrow + rr * 8;
                float2 v;
                v.x = acc[mi][ni][rr * 2 + 0] + b0;
                v.y = acc[mi][ni][rr * 2 + 1] + b1;
                *(float2*)(C + (size_t)m * DM + ncol) = v;
            }
        }
    }
}

// ============================================================================
// Flash attention: deferred-PV pipeline. 4-stage KV ring, single top barrier,
// bottom staging. Per iteration: S-mma(it) -> PV(it-1) -> softmax(it)->p(it).
// 4 warps x 32 q-rows, fp16 mma, f16x2 exp2 softmax, lazy rescale.
// ============================================================================
#define ARS 144
#define F_Q  0
#define F_KV 18432
#define F_KVS 18432          // per stage: K 9216 + V 9216
#define F_SMEM (F_KV + 4 * F_KVS)   // 92160

__device__ __forceinline__ void f_stage_kv(uint32_t sb, size_t hbase, int it,
                                           int buf, int tid)
{
    const uint32_t st = sb + F_KV + buf * F_KVS;
    const int s0 = it * 64;
    #pragma unroll
    for (int i = 0; i < 4; i++) {
        const int idx = tid + i * 128;          // 0..511
        const int row = idx >> 3, cc = idx & 7;
        const size_t src = (hbase + s0 + row) * HD + cc * 8;
        cpa(st + row * ARS + cc * 16, g_kh + src);
        cpa(st + 9216 + row * ARS + cc * 16, g_vh + src);
    }
    cp_commit();
}

__global__ __launch_bounds__(128, 2) void flash_mma(const float* __restrict__ mask)
{
    extern __shared__ char sm[];
    const uint32_t sb = su32(sm);
    const int tid = threadIdx.x, lane = tid & 31, w = tid >> 5;   // 4 warps
    const int bh = blockIdx.y, qt = blockIdx.x;
    const int g = lane >> 2, t4 = lane & 3;
    const size_t hbase = (size_t)bh * T_LEN;
    const int mnz = g_mask_nz;

    {   // stage Q (128 rows)
        const size_t qb = (hbase + qt * 128) * HD;
        #pragma unroll
        for (int i = 0; i < 8; i++) {
            const int idx = tid + i * 128;      // 0..1023
            const int row = idx >> 3, cc = idx & 7;
            cpa(sb + F_Q + row * ARS + cc * 16, g_qh + qb + (size_t)row * HD + cc * 8);
        }
        cp_commit();
    }
    f_stage_kv(sb, hbase, 0, 0, tid);
    f_stage_kv(sb, hbase, 1, 1, tid);
    cp_wait2();                                 // Q complete
    __syncthreads();

    uint32_t qf[2][4][4];
    #pragma unroll
    for (int mi = 0; mi < 2; mi++)
        #pragma unroll
        for (int j = 0; j < 4; j++)
            ldsm4(qf[mi][j], sb + F_Q + (w * 32 + mi * 16 + (lane & 15)) * ARS +
                             (j * 16 + ((lane >> 4) << 3)) * 2);

    float oacc[2][8][4];
    #pragma unroll
    for (int mi = 0; mi < 2; mi++)
        #pragma unroll
        for (int i = 0; i < 8; i++)
            #pragma unroll
            for (int v = 0; v < 4; v++) oacc[mi][i][v] = 0.f;
    float mr[2][2] = {{-1e30f, -1e30f}, {-1e30f, -1e30f}};
    float lr[2][2] = {{0.f, 0.f}, {0.f, 0.f}};
    uint32_t pp01[2][8], pp23[2][8];            // deferred p (iteration it-1)

    const int tq = qt * 128 + w * 32 + g;
    const float* mrow[2][2];
    mrow[0][0] = mask + (size_t)tq * T_LEN;
    mrow[0][1] = mrow[0][0] + (size_t)8 * T_LEN;
    mrow[1][0] = mrow[0][0] + (size_t)16 * T_LEN;
    mrow[1][1] = mrow[0][0] + (size_t)24 * T_LEN;

    #pragma unroll 1
    for (int it = 0; it < 32; it++) {
        if (it == 31) cp_wait0(); else cp_wait1();
        __syncthreads();                        // single barrier per iteration

        const uint32_t kst = sb + F_KV + (it & 3) * F_KVS;

        // ---- S' = (Q*log2e/8) K^T(it) ----
        float sacc[2][8][4];
        #pragma unroll
        for (int mi = 0; mi < 2; mi++)
            #pragma unroll
            for (int i = 0; i < 8; i++)
                #pragma unroll
                for (int v = 0; v < 4; v++) sacc[mi][i][v] = 0.f;

        #pragma unroll
        for (int j = 0; j < 4; j++) {
            uint32_t kb[8][2];
            #pragma unroll
            for (int np = 0; np < 4; np++) {
                uint32_t t[4];
                ldsm4(t, kst + (np * 16 + ((lane >> 4) << 3) + (lane & 7)) * ARS +
                         (j * 16 + (lane & 8)) * 2);
                kb[np * 2][0] = t[0]; kb[np * 2][1] = t[1];
                kb[np * 2 + 1][0] = t[2]; kb[np * 2 + 1][1] = t[3];
            }
            #pragma unroll
            for (int mi = 0; mi < 2; mi++)
                #pragma unroll
                for (int jn = 0; jn < 8; jn++)
                    mma_f16(sacc[mi][jn], qf[mi][j], kb[jn]);
        }

        // ---- deferred PV(it-1): overlaps with softmax's wait on sacc ----
        if (it > 0) {
            const uint32_t vprev = sb + F_KV + ((it - 1) & 3) * F_KVS + 9216;
            #pragma unroll
            for (int js = 0; js < 4; js++) {
                uint32_t vb[8][2];
                #pragma unroll
                for (int dp = 0; dp < 4; dp++) {
                    uint32_t t[4];
                    ldsm4t(t, vprev + (js * 16 + (lane & 15)) * ARS +
                              (dp * 16 + ((lane >> 4) << 3)) * 2);
                    vb[dp * 2][0] = t[0]; vb[dp * 2][1] = t[1];
                    vb[dp * 2 + 1][0] = t[2]; vb[dp * 2 + 1][1] = t[3];
                }
                #pragma unroll
                for (int mi = 0; mi < 2; mi++) {
                    uint32_t pf[4];
                    pf[0] = pp01[mi][2 * js];
                    pf[1] = pp23[mi][2 * js];
                    pf[2] = pp01[mi][2 * js + 1];
                    pf[3] = pp23[mi][2 * js + 1];
                    #pragma unroll
                    for (int jd = 0; jd < 8; jd++)
                        mma_f16(oacc[mi][jd], pf, vb[jd]);
                }
            }
        }

        // ---- mask + online softmax (per m-group), exp2 domain ----
        const int s0 = it * 64;
        #pragma unroll
        for (int mi = 0; mi < 2; mi++) {
            if (mnz) {
                #pragma unroll
                for (int jn = 0; jn < 8; jn++) {
                    const int sc = s0 + jn * 8 + t4 * 2;
                    float2 ma = *(const float2*)(mrow[mi][0] + sc);
                    float2 mb = *(const float2*)(mrow[mi][1] + sc);
                    sacc[mi][jn][0] = fmaf(ma.x, LOG2E, sacc[mi][jn][0]);
                    sacc[mi][jn][1] = fmaf(ma.y, LOG2E, sacc[mi][jn][1]);
                    sacc[mi][jn][2] = fmaf(mb.x, LOG2E, sacc[mi][jn][2]);
                    sacc[mi][jn][3] = fmaf(mb.y, LOG2E, sacc[mi][jn][3]);
                }
            }
            float mx0 = -1e30f, mx1 = -1e30f;
            #pragma unroll
            for (int jn = 0; jn < 8; jn++) {
                mx0 = fmaxf(mx0, fmaxf(sacc[mi][jn][0], sacc[mi][jn][1]));
                mx1 = fmaxf(mx1, fmaxf(sacc[mi][jn][2], sacc[mi][jn][3]));
            }
            mx0 = fmaxf(mx0, __shfl_xor_sync(0xffffffffu, mx0, 1));
            mx0 = fmaxf(mx0, __shfl_xor_sync(0xffffffffu, mx0, 2));
            mx1 = fmaxf(mx1, __shfl_xor_sync(0xffffffffu, mx1, 1));
            mx1 = fmaxf(mx1, __shfl_xor_sync(0xffffffffu, mx1, 2));

            if (mx0 > mr[mi][0]) {
                const float c0 = ex2(mr[mi][0] - mx0);
                mr[mi][0] = mx0;
                lr[mi][0] *= c0;
                #pragma unroll
                for (int jd = 0; jd < 8; jd++) {
                    oacc[mi][jd][0] *= c0; oacc[mi][jd][1] *= c0;
                }
            }
            if (mx1 > mr[mi][1]) {
                const float c1 = ex2(mr[mi][1] - mx1);
                mr[mi][1] = mx1;
                lr[mi][1] *= c1;
                #pragma unroll
                for (int jd = 0; jd < 8; jd++) {
                    oacc[mi][jd][2] *= c1; oacc[mi][jd][3] *= c1;
                }
            }
            #pragma unroll
            for (int jn = 0; jn < 8; jn++) {
                pp01[mi][jn] = h2ex2(fpk(sacc[mi][jn][0] - mr[mi][0],
                                         sacc[mi][jn][1] - mr[mi][0]));
                pp23[mi][jn] = h2ex2(fpk(sacc[mi][jn][2] - mr[mi][1],
                                         sacc[mi][jn][3] - mr[mi][1]));
            }
            #pragma unroll
            for (int jn = 0; jn < 8; jn += 2) {
                float2 f0 = h2f2(hadd2(pp01[mi][jn], pp01[mi][jn + 1]));
                float2 f1 = h2f2(hadd2(pp23[mi][jn], pp23[mi][jn + 1]));
                lr[mi][0] += f0.x + f0.y;
                lr[mi][1] += f1.x + f1.y;
            }
        }

        // ---- bottom staging into buffer (it+2)&3 ----
        if (it + 2 < 32) f_stage_kv(sb, hbase, it + 2, (it + 2) & 3, tid);
    }

    // ---- final PV(31) ----
    {
        const uint32_t vlast = sb + F_KV + (31 & 3) * F_KVS + 9216;
        #pragma unroll
        for (int js = 0; js < 4; js++) {
            uint32_t vb[8][2];
            #pragma unroll
            for (int dp = 0; dp < 4; dp++) {
                uint32_t t[4];
                ldsm4t(t, vlast + (js * 16 + (lane & 15)) * ARS +
                          (dp * 16 + ((lane >> 4) << 3)) * 2);
                vb[dp * 2][0] = t[0]; vb[dp * 2][1] = t[1];
                vb[dp * 2 + 1][0] = t[2]; vb[dp * 2 + 1][1] = t[3];
            }
            #pragma unroll
            for (int mi = 0; mi < 2; mi++) {
                uint32_t pf[4];
                pf[0] = pp01[mi][2 * js];
                pf[1] = pp23[mi][2 * js];
                pf[2] = pp01[mi][2 * js + 1];
                pf[3] = pp23[mi][2 * js + 1];
                #pragma unroll
                for (int jd = 0; jd < 8; jd++)
                    mma_f16(oacc[mi][jd], pf, vb[jd]);
            }
        }
    }

    const int b = bh >> 4, h = bh & 15;
    #pragma unroll
    for (int mi = 0; mi < 2; mi++) {
        float l0 = lr[mi][0], l1 = lr[mi][1];
        l0 += __shfl_xor_sync(0xffffffffu, l0, 1);
        l0 += __shfl_xor_sync(0xffffffffu, l0, 2);
        l1 += __shfl_xor_sync(0xffffffffu, l1, 1);
        l1 += __shfl_xor_sync(0xffffffffu, l1, 2);
        const float i0 = 1.0f / l0, i1 = 1.0f / l1;

        const int trow = tq + mi * 16;
        const size_t r0 = ((size_t)trow * BSZ + b) * EMB + h * HD;
        const size_t r1 = ((size_t)(trow + 8) * BSZ + b) * EMB + h * HD;
        #pragma unroll
        for (int jd = 0; jd < 8; jd++) {
            const int d = jd * 8 + t4 * 2;
            *(uint32_t*)(g_ah + r0 + d) = fpk(oacc[mi][jd][0] * i0,
                                              oacc[mi][jd][1] * i0);
            *(uint32_t*)(g_ah + r1 + d) = fpk(oacc[mi][jd][2] * i1,
                                              oacc[mi][jd][3] * i1);
        }
    }
}

// ============================================================================
// Launch
// ============================================================================
extern "C" void kernel_launch(void* const* d_in, const int* in_sizes, int n_in,
                              void* d_out, int out_size)
{
    const float* query  = (const float*)d_in[0];
    const float* key    = (const float*)d_in[1];
    const float* value  = (const float*)d_in[2];
    const float* mask   = (const float*)d_in[3];
    const float* in_w   = (const float*)d_in[4];
    const float* in_b   = (const float*)d_in[5];
    const float* out_w  = (const float*)d_in[6];
    const float* out_b  = (const float*)d_in[7];
    float* out = (float*)d_out;

    cudaFuncSetAttribute(qkv_gemm, cudaFuncAttributeMaxDynamicSharedMemorySize, G_SMEM);
    cudaFuncSetAttribute(out_gemm, cudaFuncAttributeMaxDynamicSharedMemorySize, G_SMEM);
    cudaFuncSetAttribute(flash_mma, cudaFuncAttributeMaxDynamicSharedMemorySize, F_SMEM);

    // 0) prep: convert inputs + weights + scan mask (monotonic flag, no reset)
    prep_all<<<20480, 256>>>(query, key, value, in_w, out_w, mask);

    // 1) QKV projection (fp16 mma, 128x128 tiles, 3-stage top-staged)
    qkv_gemm<<<dim3(EMB / 128, MROWS / 128, 3), 256, G_SMEM>>>(in_b);

    // 2) Attention (fp16 mma flash, deferred-PV, 4-stage KV ring)
    flash_mma<<<dim3(T_LEN / 128, BSZ * NH), 128, F_SMEM>>>(mask);

    // 3) Output projection (fp16 mma, 3-stage top-staged) -> d_out
    out_gemm<<<dim3(DM / 128, MROWS / 128), 256, G_SMEM>>>(out_b, out);
}